// round 14
// baseline (speedup 1.0000x reference)
#include <cuda_runtime.h>
#include <cuda_bf16.h>
#include <cstdint>

// ---------------------------------------------------------------------------
// MGKBertSelfAttention: B=4, S=1024, HID=768, H=12, D=32, AH=384
// out = [ctx (B,S,AH) ; probs (B,H,S,S)]  fp32
// mma.sync m16n8k16 bf16, 2-term hi/lo split (3-product, fp32-equiv precision).
// R14: barrier-free attn streaming K/V fragments directly from global (L1/L2
// broadcast across warps + co-resident same-bh CTAs). R13 chain split reverted.
// ---------------------------------------------------------------------------

namespace {
constexpr int kB = 4, kS = 1024, kHid = 768, kH = 12, kD = 32, kAH = 384;
constexpr int kBH = kB * kH;                       // 48
constexpr float kScaling = 0.17677669529663687f;   // 32^-0.5
constexpr float kC1 = 0.5f * kScaling;
constexpr float kC2 = 0.75f * kScaling;
constexpr float kLog2e = 1.4426950408889634f;
constexpr float kC1L = kC1 * kLog2e;
constexpr float kC2L = kC2 * kLog2e;
constexpr float kTC1 = 2.0f * kC1L;
constexpr float kTC2 = 2.0f * kC2L;

constexpr int kMB = (kB * kS) / 16;   // 256 m-blocks (16 rows)
constexpr int kKC = kHid / 16;        // 48 k-chunks
constexpr int kNB = kAH / 8;          // 48 n-blocks (8 cols)
}

// Scratch (device globals; allocation is forbidden)
__device__ float    g_q  [kBH * kS * kD];
__device__ uint32_t g_k1h[kBH * kS * 16];
__device__ uint32_t g_k1l[kBH * kS * 16];
__device__ uint32_t g_k2h[kBH * kS * 16];
__device__ uint32_t g_k2l[kBH * kS * 16];
__device__ uint32_t g_vth[kBH * 8 * kD * 64];
__device__ uint32_t g_vtl[kBH * 8 * kD * 64];
__device__ float    g_nq [kBH * kS];
__device__ float    g_nk1[kBH * kS];
__device__ float    g_nk2[kBH * kS];
// fragment-major pre-split operands
__device__ uint32_t g_xfh[kMB * kKC * 32 * 4];
__device__ uint32_t g_xfl[kMB * kKC * 32 * 4];
__device__ uint32_t g_wfh[4 * kNB * kKC * 32 * 2];
__device__ uint32_t g_wfl[4 * kNB * kKC * 32 * 2];

// ---------------------------------------------------------------------------
// helpers
// ---------------------------------------------------------------------------
__device__ __forceinline__ float ex2(float x) {
  float r;
  asm("ex2.approx.f32 %0, %1;" : "=f"(r) : "f"(x));
  return r;
}
__device__ __forceinline__ void split2(float x, float y, uint32_t& h, uint32_t& l) {
  __nv_bfloat16 bx = __float2bfloat16_rn(x);
  __nv_bfloat16 by = __float2bfloat16_rn(y);
  float rx = x - __bfloat162float(bx);
  float ry = y - __bfloat162float(by);
  __nv_bfloat16 lx = __float2bfloat16_rn(rx);
  __nv_bfloat16 ly = __float2bfloat16_rn(ry);
  h = (uint32_t)__bfloat16_as_ushort(bx) | ((uint32_t)__bfloat16_as_ushort(by) << 16);
  l = (uint32_t)__bfloat16_as_ushort(lx) | ((uint32_t)__bfloat16_as_ushort(ly) << 16);
}
__device__ __forceinline__ void mma_bf16(float* c, const uint32_t* a,
                                         uint32_t b0, uint32_t b1) {
  asm volatile(
      "mma.sync.aligned.m16n8k16.row.col.f32.bf16.bf16.f32 "
      "{%0,%1,%2,%3}, {%4,%5,%6,%7}, {%8,%9}, {%0,%1,%2,%3};\n"
      : "+f"(c[0]), "+f"(c[1]), "+f"(c[2]), "+f"(c[3])
      : "r"(a[0]), "r"(a[1]), "r"(a[2]), "r"(a[3]), "r"(b0), "r"(b1));
}

// ---------------------------------------------------------------------------
// Pre-split kernel (unchanged from R12)
// ---------------------------------------------------------------------------
__global__ __launch_bounds__(256) void presplit_kernel(
    const float* __restrict__ X,
    const float* __restrict__ Wq, const float* __restrict__ Wk1,
    const float* __restrict__ Wk2, const float* __restrict__ Wv)
{
  const int wg = blockIdx.x * 8 + (threadIdx.x >> 5);
  const int lane = threadIdx.x & 31;
  const int g = lane >> 2, t = lane & 3;

  if (wg < kMB * kKC) {
    const int mb = wg / kKC, kc = wg % kKC;
    const float* p0 = X + (size_t)(mb * 16 + g) * kHid + kc * 16 + 2 * t;
    const float* p1 = p0 + 8 * kHid;
    float2 v00 = *(const float2*)p0;
    float2 v01 = *(const float2*)(p0 + 8);
    float2 v10 = *(const float2*)p1;
    float2 v11 = *(const float2*)(p1 + 8);
    uint4 hv, lv;
    split2(v00.x, v00.y, hv.x, lv.x);
    split2(v10.x, v10.y, hv.y, lv.y);
    split2(v01.x, v01.y, hv.z, lv.z);
    split2(v11.x, v11.y, hv.w, lv.w);
    const size_t o = ((size_t)wg * 32 + lane) * 4;
    *(uint4*)&g_xfh[o] = hv;
    *(uint4*)&g_xfl[o] = lv;
  } else {
    const int r = wg - kMB * kKC;
    if (r >= 4 * kNB * kKC) return;
    const int sel = r / (kNB * kKC);
    const int rr = r % (kNB * kKC);
    const int nb = rr / kKC, kc = rr % kKC;
    const float* W = (sel == 0) ? Wq : (sel == 1) ? Wk1 : (sel == 2) ? Wk2 : Wv;
    const float* p = W + (size_t)(nb * 8 + g) * kHid + kc * 16 + 2 * t;
    float2 v0 = *(const float2*)p;
    float2 v1 = *(const float2*)(p + 8);
    uint32_t h0, l0, h1, l1;
    split2(v0.x, v0.y, h0, l0);
    split2(v1.x, v1.y, h1, l1);
    const size_t o = ((size_t)r * 32 + lane) * 2;
    g_wfh[o] = h0; g_wfh[o + 1] = h1;
    g_wfl[o] = l0; g_wfl[o + 1] = l1;
  }
}

// ---------------------------------------------------------------------------
// Streaming projection GEMM (unchanged from R12)
// ---------------------------------------------------------------------------
__global__ __launch_bounds__(256) void proj_kernel(
    const float* __restrict__ bq, const float* __restrict__ bk1,
    const float* __restrict__ bk2, const float* __restrict__ bv)
{
  const int sel = blockIdx.z;
  const float* bias = (sel == 0) ? bq : (sel == 1) ? bk1 : (sel == 2) ? bk2 : bv;

  const int tid = threadIdx.x;
  const int w = tid >> 5, lane = tid & 31;
  const int g = lane >> 2, t = lane & 3;
  const int wm = (w & 3) * 32, wn = (w >> 2) * 32;
  const int m0 = blockIdx.y * 128, n0 = blockIdx.x * 64;

  const int mb0 = (m0 + wm) >> 4;
  const int nb0 = (n0 + wn) >> 3;
  const size_t xbase0 = (((size_t)mb0 * kKC) * 32 + lane) * 4;
  const size_t xbase1 = ((((size_t)mb0 + 1) * kKC) * 32 + lane) * 4;
  const size_t wsel = (size_t)sel * kNB * kKC * 64;
  size_t wbase[4];
#pragma unroll
  for (int nc = 0; nc < 4; nc++)
    wbase[nc] = wsel + (((size_t)(nb0 + nc) * kKC) * 32 + lane) * 2;

  float c[2][4][4];
#pragma unroll
  for (int i = 0; i < 2; i++)
#pragma unroll
    for (int j = 0; j < 4; j++)
#pragma unroll
      for (int k = 0; k < 4; k++) c[i][j][k] = 0.f;

#pragma unroll 2
  for (int kc = 0; kc < kKC; kc++) {
    uint4 ah[2], al[2];
    ah[0] = *(const uint4*)&g_xfh[xbase0 + (size_t)kc * 128];
    al[0] = *(const uint4*)&g_xfl[xbase0 + (size_t)kc * 128];
    ah[1] = *(const uint4*)&g_xfh[xbase1 + (size_t)kc * 128];
    al[1] = *(const uint4*)&g_xfl[xbase1 + (size_t)kc * 128];
#pragma unroll
    for (int nc = 0; nc < 4; nc++) {
      const size_t wo = wbase[nc] + (size_t)kc * 64;
      uint2 bh = *(const uint2*)&g_wfh[wo];
      uint2 bl = *(const uint2*)&g_wfl[wo];
#pragma unroll
      for (int tm = 0; tm < 2; tm++) {
        mma_bf16(c[tm][nc], (const uint32_t*)&ah[tm], bh.x, bh.y);
        mma_bf16(c[tm][nc], (const uint32_t*)&ah[tm], bl.x, bl.y);
        mma_bf16(c[tm][nc], (const uint32_t*)&al[tm], bh.x, bh.y);
      }
    }
  }

  const int head = (n0 + wn) >> 5;
#pragma unroll
  for (int nc = 0; nc < 4; nc++) {
    const float bb0 = bias[n0 + wn + nc * 8 + 2 * t];
    const float bb1 = bias[n0 + wn + nc * 8 + 2 * t + 1];
#pragma unroll
    for (int tm = 0; tm < 2; tm++) {
      c[tm][nc][0] += bb0; c[tm][nc][1] += bb1;
      c[tm][nc][2] += bb0; c[tm][nc][3] += bb1;
    }
  }

  if (sel < 3) {
    float* nrm = (sel == 0) ? g_nq : (sel == 1) ? g_nk1 : g_nk2;
    float ps[2][2] = {{0.f, 0.f}, {0.f, 0.f}};
#pragma unroll
    for (int tm = 0; tm < 2; tm++)
#pragma unroll
      for (int nc = 0; nc < 4; nc++) {
        ps[tm][0] = fmaf(c[tm][nc][0], c[tm][nc][0],
                    fmaf(c[tm][nc][1], c[tm][nc][1], ps[tm][0]));
        ps[tm][1] = fmaf(c[tm][nc][2], c[tm][nc][2],
                    fmaf(c[tm][nc][3], c[tm][nc][3], ps[tm][1]));
      }
#pragma unroll
    for (int tm = 0; tm < 2; tm++)
#pragma unroll
      for (int hh = 0; hh < 2; hh++) {
#pragma unroll
        for (int o = 1; o < 4; o <<= 1)
          ps[tm][hh] += __shfl_xor_sync(0xffffffffu, ps[tm][hh], o);
      }
    if (t == 0) {
#pragma unroll
      for (int tm = 0; tm < 2; tm++)
#pragma unroll
        for (int hh = 0; hh < 2; hh++) {
          const int r = m0 + wm + tm * 16 + g + hh * 8;
          const int b = r >> 10, s = r & 1023;
          nrm[(b * kH + head) * kS + s] = ps[tm][hh];
        }
    }
  }

  if (sel == 0) {
#pragma unroll
    for (int tm = 0; tm < 2; tm++)
#pragma unroll
      for (int nc = 0; nc < 4; nc++) {
        const int d = nc * 8 + 2 * t;
        const int r0 = m0 + wm + tm * 16 + g;
        {
          const int b = r0 >> 10, s = r0 & 1023;
          *(float2*)&g_q[(((size_t)b * kH + head) * kS + s) * kD + d] =
              make_float2(c[tm][nc][0], c[tm][nc][1]);
        }
        {
          const int r1 = r0 + 8;
          const int b = r1 >> 10, s = r1 & 1023;
          *(float2*)&g_q[(((size_t)b * kH + head) * kS + s) * kD + d] =
              make_float2(c[tm][nc][2], c[tm][nc][3]);
        }
      }
  } else if (sel < 3) {
    uint32_t* outh = (sel == 1) ? g_k1h : g_k2h;
    uint32_t* outl = (sel == 1) ? g_k1l : g_k2l;
#pragma unroll
    for (int tm = 0; tm < 2; tm++)
#pragma unroll
      for (int nc = 0; nc < 4; nc++) {
        const int pos = t * 4 + nc;
        const int r0 = m0 + wm + tm * 16 + g;
        uint32_t h, l;
        {
          const int b = r0 >> 10, s = r0 & 1023;
          split2(c[tm][nc][0], c[tm][nc][1], h, l);
          const size_t o = ((size_t)(b * kH + head) * kS + s) * 16 + pos;
          outh[o] = h; outl[o] = l;
        }
        {
          const int r1 = r0 + 8;
          const int b = r1 >> 10, s = r1 & 1023;
          split2(c[tm][nc][2], c[tm][nc][3], h, l);
          const size_t o = ((size_t)(b * kH + head) * kS + s) * 16 + pos;
          outh[o] = h; outl[o] = l;
        }
      }
  } else {
#pragma unroll
    for (int tm = 0; tm < 2; tm++)
#pragma unroll
      for (int nc = 0; nc < 4; nc++)
#pragma unroll
        for (int hh = 0; hh < 2; hh++) {
          float v0 = c[tm][nc][hh * 2];
          float v1 = c[tm][nc][hh * 2 + 1];
          float v0o = __shfl_down_sync(0xffffffffu, v0, 4);
          float v1o = __shfl_down_sync(0xffffffffu, v1, 4);
          if ((g & 1) == 0) {
            const int m = m0 + wm + tm * 16 + g + hh * 8;
            const int b = m >> 10, s = m & 1023;
            const int kt = s >> 7;
            const int jp = (s & 127) >> 1;
            const int pos = (jp & ~7) + ((jp & 3) << 1) + ((jp >> 2) & 1);
            const int d = nc * 8 + 2 * t;
            const size_t base = ((size_t)(b * kH + head) * 8 + kt) * kD;
            uint32_t h0, l0, h1, l1;
            split2(v0, v0o, h0, l0);
            split2(v1, v1o, h1, l1);
            g_vth[(base + d) * 64 + pos] = h0;
            g_vtl[(base + d) * 64 + pos] = l0;
            g_vth[(base + d + 1) * 64 + pos] = h1;
            g_vtl[(base + d + 1) * 64 + pos] = l1;
          }
        }
  }
}

// ---------------------------------------------------------------------------
// Fused attention, R14: barrier-free main loops; K/V fragments streamed from
// global (fragment-major layouts; L1 broadcast across warps/CTAs of one bh).
// score6 reverted to single-accumulator chain (R12).
// ---------------------------------------------------------------------------
__device__ __forceinline__ void score6(float* c,
                                       const uint32_t aqh[2][4],
                                       const uint32_t aql[2][4],
                                       const uint32_t* __restrict__ Kh,
                                       const uint32_t* __restrict__ Kl,
                                       size_t rb) {
  uint4 fh = *(const uint4*)&Kh[rb];
  uint4 fl = *(const uint4*)&Kl[rb];
  c[0] = c[1] = c[2] = c[3] = 0.f;
  mma_bf16(c, aqh[0], fh.x, fh.y);
  mma_bf16(c, aqh[0], fl.x, fl.y);
  mma_bf16(c, aql[0], fh.x, fh.y);
  mma_bf16(c, aqh[1], fh.z, fh.w);
  mma_bf16(c, aqh[1], fl.z, fl.w);
  mma_bf16(c, aql[1], fh.z, fh.w);
}

__global__ __launch_bounds__(256, 3) void attn_kernel(
    const float* __restrict__ mask, const float* __restrict__ pi,
    float* __restrict__ out_ctx, float* __restrict__ out_probs)
{
  __shared__ float colc1[kS];
  __shared__ float colc2[kS];
  __shared__ float qst[128 * 33];

  const int tid = threadIdx.x;
  const int w = tid >> 5, lane = tid & 31;
  const int g = lane >> 2, t = lane & 3;
  const int R0 = w * 16 + g, R1 = R0 + 8;

  const int qt = blockIdx.x, bh = blockIdx.y;
  const int b = bh / kH, h = bh % kH;
  const int q0 = qt * 128;
  const int nbase = bh * kS;
  const size_t gbase = (size_t)bh * kS * kD;

  const float pi0 = fminf(fmaxf(pi[h],      1e-6f), 2.0f);
  const float pi1 = fminf(fmaxf(pi[kH + h], 1e-6f), 2.0f);
  const float lp0 = __log2f(pi0), lp1 = __log2f(pi1);

  for (int i = tid; i < kS; i += 256) {
    const float mk = mask[b * kS + i] * kLog2e;
    colc1[i] = fmaf(-kC1L, g_nk1[nbase + i], mk);
    colc2[i] = fmaf(-kC2L, g_nk2[nbase + i], mk);
  }
  for (int i = tid; i < 1024; i += 256) {
    const int j = i >> 3, dg = (i & 7) * 4;
    float4 v = *(const float4*)&g_q[gbase + (size_t)(q0 + j) * kD + dg];
    qst[j * 33 + dg + 0] = v.x; qst[j * 33 + dg + 1] = v.y;
    qst[j * 33 + dg + 2] = v.z; qst[j * 33 + dg + 3] = v.w;
  }
  __syncthreads();

  uint32_t aqh[2][4], aql[2][4];
#pragma unroll
  for (int ks = 0; ks < 2; ks++) {
    const int d0 = 16 * ks + 2 * t;
    split2(qst[R0 * 33 + d0],     qst[R0 * 33 + d0 + 1], aqh[ks][0], aql[ks][0]);
    split2(qst[R1 * 33 + d0],     qst[R1 * 33 + d0 + 1], aqh[ks][1], aql[ks][1]);
    split2(qst[R0 * 33 + d0 + 8], qst[R0 * 33 + d0 + 9], aqh[ks][2], aql[ks][2]);
    split2(qst[R1 * 33 + d0 + 8], qst[R1 * 33 + d0 + 9], aqh[ks][3], aql[ks][3]);
  }
  const float nq0 = g_nq[nbase + q0 + R0];
  const float nq1 = g_nq[nbase + q0 + R1];
  const float rq1a = -kC1L * nq0, rq1b = -kC1L * nq1;
  const float rq2a = -kC2L * nq0, rq2b = -kC2L * nq1;

  // global fragment bases for this bh (u32 units)
  const size_t kfb = (size_t)nbase * 16;   // + (row)*16 + t*4

  // ====== pass 1: barrier-free, 128 column-tiles ======
  float m1a = -1e30f, m1b = -1e30f, m2a = -1e30f, m2b = -1e30f;
  float l1a = 0.f, l1b = 0.f, l2a = 0.f, l2b = 0.f;

#pragma unroll 2
  for (int nt = 0; nt < 128; nt++) {
    const size_t rb = kfb + (size_t)(nt * 8 + g) * 16 + t * 4;
    const int col = nt * 8 + 2 * t;
    const float2 cc1 = *(const float2*)&colc1[col];
    const float2 cc2 = *(const float2*)&colc2[col];
    float c1[4], c2[4];
    score6(c1, aqh, aql, g_k1h, g_k1l, rb);
    score6(c2, aqh, aql, g_k2h, g_k2l, rb);
    {
      float s0 = fmaf(kTC1, c1[0], cc1.x + rq1a);
      float s1 = fmaf(kTC1, c1[1], cc1.y + rq1a);
      m1a = fmaxf(m1a, fmaxf(s0, s1));
      l1a += ex2(s0) + ex2(s1);
    }
    {
      float s0 = fmaf(kTC1, c1[2], cc1.x + rq1b);
      float s1 = fmaf(kTC1, c1[3], cc1.y + rq1b);
      m1b = fmaxf(m1b, fmaxf(s0, s1));
      l1b += ex2(s0) + ex2(s1);
    }
    {
      float s0 = fmaf(kTC2, c2[0], cc2.x + rq2a);
      float s1 = fmaf(kTC2, c2[1], cc2.y + rq2a);
      m2a = fmaxf(m2a, fmaxf(s0, s1));
      l2a += ex2(s0) + ex2(s1);
    }
    {
      float s0 = fmaf(kTC2, c2[2], cc2.x + rq2b);
      float s1 = fmaf(kTC2, c2[3], cc2.y + rq2b);
      m2b = fmaxf(m2b, fmaxf(s0, s1));
      l2b += ex2(s0) + ex2(s1);
    }
  }
#pragma unroll
  for (int o = 1; o < 4; o <<= 1) {
    m1a = fmaxf(m1a, __shfl_xor_sync(0xffffffffu, m1a, o));
    m1b = fmaxf(m1b, __shfl_xor_sync(0xffffffffu, m1b, o));
    m2a = fmaxf(m2a, __shfl_xor_sync(0xffffffffu, m2a, o));
    m2b = fmaxf(m2b, __shfl_xor_sync(0xffffffffu, m2b, o));
    l1a += __shfl_xor_sync(0xffffffffu, l1a, o);
    l1b += __shfl_xor_sync(0xffffffffu, l1b, o);
    l2a += __shfl_xor_sync(0xffffffffu, l2a, o);
    l2b += __shfl_xor_sync(0xffffffffu, l2b, o);
  }
  const float inv0 = 1.0f / (pi0 * ex2(-m1a) * l1a +
                             pi1 * ex2(-m2a) * l2a + 1e-6f);
  const float inv1 = 1.0f / (pi0 * ex2(-m1b) * l1b +
                             pi1 * ex2(-m2b) * l2b + 1e-6f);
  const float rq1a2 = rq1a + lp0 - m1a, rq1b2 = rq1b + lp0 - m1b;
  const float rq2a2 = rq2a + lp1 - m2a, rq2b2 = rq2b + lp1 - m2b;

  // ====== pass 2: barrier-free; V fragments streamed from global ======
  float cctx[4][4];
#pragma unroll
  for (int i = 0; i < 4; i++)
#pragma unroll
    for (int j = 0; j < 4; j++) cctx[i][j] = 0.f;

  uint32_t eh[4], el[4];

  for (int kt = 0; kt < 8; kt++) {
    const size_t vg = ((size_t)bh * 8 + kt) * (kD * 64);
#pragma unroll 2
    for (int nt = 0; nt < 16; nt++) {
      const size_t rb = kfb + (size_t)(kt * 128 + nt * 8 + g) * 16 + t * 4;
      const int col = kt * 128 + nt * 8 + 2 * t;
      const float2 cc1 = *(const float2*)&colc1[col];
      const float2 cc2 = *(const float2*)&colc2[col];
      float c1[4], c2[4];
      score6(c1, aqh, aql, g_k1h, g_k1l, rb);
      score6(c2, aqh, aql, g_k2h, g_k2l, rb);
      float p00 = (ex2(fmaf(kTC1, c1[0], cc1.x + rq1a2))
                 + ex2(fmaf(kTC2, c2[0], cc2.x + rq2a2))) * inv0;
      float p01 = (ex2(fmaf(kTC1, c1[1], cc1.y + rq1a2))
                 + ex2(fmaf(kTC2, c2[1], cc2.y + rq2a2))) * inv0;
      float p10 = (ex2(fmaf(kTC1, c1[2], cc1.x + rq1b2))
                 + ex2(fmaf(kTC2, c2[2], cc2.x + rq2b2))) * inv1;
      float p11 = (ex2(fmaf(kTC1, c1[3], cc1.y + rq1b2))
                 + ex2(fmaf(kTC2, c2[3], cc2.y + rq2b2))) * inv1;

      const size_t pb = ((size_t)bh * kS + q0 + R0) * kS + col;
      __stcs((float2*)&out_probs[pb], make_float2(p00, p01));
      __stcs((float2*)&out_probs[pb + 8 * kS], make_float2(p10, p11));

      if ((nt & 1) == 0) {
        split2(p00, p01, eh[0], el[0]);
        split2(p10, p11, eh[1], el[1]);
      } else {
        split2(p00, p01, eh[2], el[2]);
        split2(p10, p11, eh[3], el[3]);
        const int ks = nt >> 1;
#pragma unroll
        for (int nd = 0; nd < 4; nd++) {
          const size_t vb = vg + (size_t)(nd * 8 + g) * 64 + 8 * ks + 2 * t;
          uint2 vh = *(const uint2*)&g_vth[vb];
          uint2 vl = *(const uint2*)&g_vtl[vb];
          mma_bf16(cctx[nd], eh, vh.x, vh.y);
          mma_bf16(cctx[nd], eh, vl.x, vl.y);
          mma_bf16(cctx[nd], el, vh.x, vh.y);
        }
      }
    }
  }

#pragma unroll
  for (int nd = 0; nd < 4; nd++) {
    const int d = nd * 8 + 2 * t;
    *(float2*)&out_ctx[((size_t)b * kS + q0 + R0) * kAH + h * kD + d] =
        make_float2(cctx[nd][0], cctx[nd][1]);
    *(float2*)&out_ctx[((size_t)b * kS + q0 + R1) * kAH + h * kD + d] =
        make_float2(cctx[nd][2], cctx[nd][3]);
  }
}

// ---------------------------------------------------------------------------
extern "C" void kernel_launch(void* const* d_in, const int* in_sizes, int n_in,
                              void* d_out, int out_size) {
  (void)in_sizes; (void)n_in; (void)out_size;
  const float* hs   = (const float*)d_in[0];
  const float* mask = (const float*)d_in[1];
  const float* Wq   = (const float*)d_in[2];
  const float* bq   = (const float*)d_in[3];
  const float* Wk1  = (const float*)d_in[4];
  const float* bk1  = (const float*)d_in[5];
  const float* Wk2  = (const float*)d_in[6];
  const float* bk2  = (const float*)d_in[7];
  const float* Wv   = (const float*)d_in[8];
  const float* bv   = (const float*)d_in[9];
  const float* pi   = (const float*)d_in[10];

  float* out_ctx   = (float*)d_out;
  float* out_probs = out_ctx + (size_t)kB * kS * kAH;

  const int total_warps = kMB * kKC + 4 * kNB * kKC;
  presplit_kernel<<<(total_warps + 7) / 8, 256>>>(hs, Wq, Wk1, Wk2, Wv);

  dim3 pgrid(kAH / 64, (kB * kS) / 128, 4);   // (6, 32, 4) = 768 CTAs
  proj_kernel<<<pgrid, 256>>>(bq, bk1, bk2, bv);
  attn_kernel<<<dim3(kS / 128, kBH), 256>>>(mask, pi, out_ctx, out_probs);
}

// round 15
// speedup vs baseline: 1.0532x; 1.0532x over previous
#include <cuda_runtime.h>
#include <cuda_bf16.h>
#include <cstdint>

// ---------------------------------------------------------------------------
// MGKBertSelfAttention: B=4, S=1024, HID=768, H=12, D=32, AH=384
// out = [ctx (B,S,AH) ; probs (B,H,S,S)]  fp32
// mma.sync m16n8k16 bf16, 2-term hi/lo split (3-product, fp32-equiv precision).
// R15: R12 base + cp.async double-buffered K tiles (latency hidden behind
// compute); V streamed from global (frees smem for the second K buffer).
// ---------------------------------------------------------------------------

namespace {
constexpr int kB = 4, kS = 1024, kHid = 768, kH = 12, kD = 32, kAH = 384;
constexpr int kBH = kB * kH;                       // 48
constexpr float kScaling = 0.17677669529663687f;   // 32^-0.5
constexpr float kC1 = 0.5f * kScaling;
constexpr float kC2 = 0.75f * kScaling;
constexpr float kLog2e = 1.4426950408889634f;
constexpr float kC1L = kC1 * kLog2e;
constexpr float kC2L = kC2 * kLog2e;
constexpr float kTC1 = 2.0f * kC1L;
constexpr float kTC2 = 2.0f * kC2L;

constexpr int kMB = (kB * kS) / 16;   // 256 m-blocks (16 rows)
constexpr int kKC = kHid / 16;        // 48 k-chunks
constexpr int kNB = kAH / 8;          // 48 n-blocks (8 cols)

// attn smem layout (u32 units): colc tables + two K-tile buffers
constexpr int U_COLC1 = 0;            // 1024
constexpr int U_COLC2 = 1024;         // 1024
constexpr int U_BUF0  = 2048;         // 8192 (K1h|K1l|K2h|K2l, 2048 each)
constexpr int U_BUF1  = 10240;        // 8192 (Q stage aliases this pre-loop)
constexpr int kAttnSmemU32 = 18432;
constexpr int kAttnSmemBytes = kAttnSmemU32 * 4;   // 73728 B (x3 = 216 KB)
}

// Scratch (device globals; allocation is forbidden)
__device__ float    g_q  [kBH * kS * kD];
__device__ uint32_t g_k1h[kBH * kS * 16];
__device__ uint32_t g_k1l[kBH * kS * 16];
__device__ uint32_t g_k2h[kBH * kS * 16];
__device__ uint32_t g_k2l[kBH * kS * 16];
__device__ uint32_t g_vth[kBH * 8 * kD * 64];
__device__ uint32_t g_vtl[kBH * 8 * kD * 64];
__device__ float    g_nq [kBH * kS];
__device__ float    g_nk1[kBH * kS];
__device__ float    g_nk2[kBH * kS];
// fragment-major pre-split operands
__device__ uint32_t g_xfh[kMB * kKC * 32 * 4];
__device__ uint32_t g_xfl[kMB * kKC * 32 * 4];
__device__ uint32_t g_wfh[4 * kNB * kKC * 32 * 2];
__device__ uint32_t g_wfl[4 * kNB * kKC * 32 * 2];

// ---------------------------------------------------------------------------
// helpers
// ---------------------------------------------------------------------------
__device__ __forceinline__ float ex2(float x) {
  float r;
  asm("ex2.approx.f32 %0, %1;" : "=f"(r) : "f"(x));
  return r;
}
__device__ __forceinline__ void split2(float x, float y, uint32_t& h, uint32_t& l) {
  __nv_bfloat16 bx = __float2bfloat16_rn(x);
  __nv_bfloat16 by = __float2bfloat16_rn(y);
  float rx = x - __bfloat162float(bx);
  float ry = y - __bfloat162float(by);
  __nv_bfloat16 lx = __float2bfloat16_rn(rx);
  __nv_bfloat16 ly = __float2bfloat16_rn(ry);
  h = (uint32_t)__bfloat16_as_ushort(bx) | ((uint32_t)__bfloat16_as_ushort(by) << 16);
  l = (uint32_t)__bfloat16_as_ushort(lx) | ((uint32_t)__bfloat16_as_ushort(ly) << 16);
}
__device__ __forceinline__ void mma_bf16(float* c, const uint32_t* a,
                                         uint32_t b0, uint32_t b1) {
  asm volatile(
      "mma.sync.aligned.m16n8k16.row.col.f32.bf16.bf16.f32 "
      "{%0,%1,%2,%3}, {%4,%5,%6,%7}, {%8,%9}, {%0,%1,%2,%3};\n"
      : "+f"(c[0]), "+f"(c[1]), "+f"(c[2]), "+f"(c[3])
      : "r"(a[0]), "r"(a[1]), "r"(a[2]), "r"(a[3]), "r"(b0), "r"(b1));
}
__device__ __forceinline__ uint32_t smem_addr_of(const void* p) {
  uint32_t a;
  asm("{ .reg .u64 t; cvta.to.shared.u64 t, %1; cvt.u32.u64 %0, t; }"
      : "=r"(a) : "l"(p));
  return a;
}
__device__ __forceinline__ void cp_async16(uint32_t sa, const void* gp) {
  asm volatile("cp.async.cg.shared.global [%0], [%1], 16;"
               :: "r"(sa), "l"(gp) : "memory");
}
__device__ __forceinline__ void cp_commit() {
  asm volatile("cp.async.commit_group;" ::: "memory");
}
__device__ __forceinline__ void cp_wait1() {
  asm volatile("cp.async.wait_group 1;" ::: "memory");
}
__device__ __forceinline__ void cp_wait0() {
  asm volatile("cp.async.wait_group 0;" ::: "memory");
}

// ---------------------------------------------------------------------------
// Pre-split kernel (unchanged from R12)
// ---------------------------------------------------------------------------
__global__ __launch_bounds__(256) void presplit_kernel(
    const float* __restrict__ X,
    const float* __restrict__ Wq, const float* __restrict__ Wk1,
    const float* __restrict__ Wk2, const float* __restrict__ Wv)
{
  const int wg = blockIdx.x * 8 + (threadIdx.x >> 5);
  const int lane = threadIdx.x & 31;
  const int g = lane >> 2, t = lane & 3;

  if (wg < kMB * kKC) {
    const int mb = wg / kKC, kc = wg % kKC;
    const float* p0 = X + (size_t)(mb * 16 + g) * kHid + kc * 16 + 2 * t;
    const float* p1 = p0 + 8 * kHid;
    float2 v00 = *(const float2*)p0;
    float2 v01 = *(const float2*)(p0 + 8);
    float2 v10 = *(const float2*)p1;
    float2 v11 = *(const float2*)(p1 + 8);
    uint4 hv, lv;
    split2(v00.x, v00.y, hv.x, lv.x);
    split2(v10.x, v10.y, hv.y, lv.y);
    split2(v01.x, v01.y, hv.z, lv.z);
    split2(v11.x, v11.y, hv.w, lv.w);
    const size_t o = ((size_t)wg * 32 + lane) * 4;
    *(uint4*)&g_xfh[o] = hv;
    *(uint4*)&g_xfl[o] = lv;
  } else {
    const int r = wg - kMB * kKC;
    if (r >= 4 * kNB * kKC) return;
    const int sel = r / (kNB * kKC);
    const int rr = r % (kNB * kKC);
    const int nb = rr / kKC, kc = rr % kKC;
    const float* W = (sel == 0) ? Wq : (sel == 1) ? Wk1 : (sel == 2) ? Wk2 : Wv;
    const float* p = W + (size_t)(nb * 8 + g) * kHid + kc * 16 + 2 * t;
    float2 v0 = *(const float2*)p;
    float2 v1 = *(const float2*)(p + 8);
    uint32_t h0, l0, h1, l1;
    split2(v0.x, v0.y, h0, l0);
    split2(v1.x, v1.y, h1, l1);
    const size_t o = ((size_t)r * 32 + lane) * 2;
    g_wfh[o] = h0; g_wfh[o + 1] = h1;
    g_wfl[o] = l0; g_wfl[o + 1] = l1;
  }
}

// ---------------------------------------------------------------------------
// Streaming projection GEMM (unchanged from R12)
// ---------------------------------------------------------------------------
__global__ __launch_bounds__(256) void proj_kernel(
    const float* __restrict__ bq, const float* __restrict__ bk1,
    const float* __restrict__ bk2, const float* __restrict__ bv)
{
  const int sel = blockIdx.z;
  const float* bias = (sel == 0) ? bq : (sel == 1) ? bk1 : (sel == 2) ? bk2 : bv;

  const int tid = threadIdx.x;
  const int w = tid >> 5, lane = tid & 31;
  const int g = lane >> 2, t = lane & 3;
  const int wm = (w & 3) * 32, wn = (w >> 2) * 32;
  const int m0 = blockIdx.y * 128, n0 = blockIdx.x * 64;

  const int mb0 = (m0 + wm) >> 4;
  const int nb0 = (n0 + wn) >> 3;
  const size_t xbase0 = (((size_t)mb0 * kKC) * 32 + lane) * 4;
  const size_t xbase1 = ((((size_t)mb0 + 1) * kKC) * 32 + lane) * 4;
  const size_t wsel = (size_t)sel * kNB * kKC * 64;
  size_t wbase[4];
#pragma unroll
  for (int nc = 0; nc < 4; nc++)
    wbase[nc] = wsel + (((size_t)(nb0 + nc) * kKC) * 32 + lane) * 2;

  float c[2][4][4];
#pragma unroll
  for (int i = 0; i < 2; i++)
#pragma unroll
    for (int j = 0; j < 4; j++)
#pragma unroll
      for (int k = 0; k < 4; k++) c[i][j][k] = 0.f;

#pragma unroll 2
  for (int kc = 0; kc < kKC; kc++) {
    uint4 ah[2], al[2];
    ah[0] = *(const uint4*)&g_xfh[xbase0 + (size_t)kc * 128];
    al[0] = *(const uint4*)&g_xfl[xbase0 + (size_t)kc * 128];
    ah[1] = *(const uint4*)&g_xfh[xbase1 + (size_t)kc * 128];
    al[1] = *(const uint4*)&g_xfl[xbase1 + (size_t)kc * 128];
#pragma unroll
    for (int nc = 0; nc < 4; nc++) {
      const size_t wo = wbase[nc] + (size_t)kc * 64;
      uint2 bh = *(const uint2*)&g_wfh[wo];
      uint2 bl = *(const uint2*)&g_wfl[wo];
#pragma unroll
      for (int tm = 0; tm < 2; tm++) {
        mma_bf16(c[tm][nc], (const uint32_t*)&ah[tm], bh.x, bh.y);
        mma_bf16(c[tm][nc], (const uint32_t*)&ah[tm], bl.x, bl.y);
        mma_bf16(c[tm][nc], (const uint32_t*)&al[tm], bh.x, bh.y);
      }
    }
  }

  const int head = (n0 + wn) >> 5;
#pragma unroll
  for (int nc = 0; nc < 4; nc++) {
    const float bb0 = bias[n0 + wn + nc * 8 + 2 * t];
    const float bb1 = bias[n0 + wn + nc * 8 + 2 * t + 1];
#pragma unroll
    for (int tm = 0; tm < 2; tm++) {
      c[tm][nc][0] += bb0; c[tm][nc][1] += bb1;
      c[tm][nc][2] += bb0; c[tm][nc][3] += bb1;
    }
  }

  if (sel < 3) {
    float* nrm = (sel == 0) ? g_nq : (sel == 1) ? g_nk1 : g_nk2;
    float ps[2][2] = {{0.f, 0.f}, {0.f, 0.f}};
#pragma unroll
    for (int tm = 0; tm < 2; tm++)
#pragma unroll
      for (int nc = 0; nc < 4; nc++) {
        ps[tm][0] = fmaf(c[tm][nc][0], c[tm][nc][0],
                    fmaf(c[tm][nc][1], c[tm][nc][1], ps[tm][0]));
        ps[tm][1] = fmaf(c[tm][nc][2], c[tm][nc][2],
                    fmaf(c[tm][nc][3], c[tm][nc][3], ps[tm][1]));
      }
#pragma unroll
    for (int tm = 0; tm < 2; tm++)
#pragma unroll
      for (int hh = 0; hh < 2; hh++) {
#pragma unroll
        for (int o = 1; o < 4; o <<= 1)
          ps[tm][hh] += __shfl_xor_sync(0xffffffffu, ps[tm][hh], o);
      }
    if (t == 0) {
#pragma unroll
      for (int tm = 0; tm < 2; tm++)
#pragma unroll
        for (int hh = 0; hh < 2; hh++) {
          const int r = m0 + wm + tm * 16 + g + hh * 8;
          const int b = r >> 10, s = r & 1023;
          nrm[(b * kH + head) * kS + s] = ps[tm][hh];
        }
    }
  }

  if (sel == 0) {
#pragma unroll
    for (int tm = 0; tm < 2; tm++)
#pragma unroll
      for (int nc = 0; nc < 4; nc++) {
        const int d = nc * 8 + 2 * t;
        const int r0 = m0 + wm + tm * 16 + g;
        {
          const int b = r0 >> 10, s = r0 & 1023;
          *(float2*)&g_q[(((size_t)b * kH + head) * kS + s) * kD + d] =
              make_float2(c[tm][nc][0], c[tm][nc][1]);
        }
        {
          const int r1 = r0 + 8;
          const int b = r1 >> 10, s = r1 & 1023;
          *(float2*)&g_q[(((size_t)b * kH + head) * kS + s) * kD + d] =
              make_float2(c[tm][nc][2], c[tm][nc][3]);
        }
      }
  } else if (sel < 3) {
    uint32_t* outh = (sel == 1) ? g_k1h : g_k2h;
    uint32_t* outl = (sel == 1) ? g_k1l : g_k2l;
#pragma unroll
    for (int tm = 0; tm < 2; tm++)
#pragma unroll
      for (int nc = 0; nc < 4; nc++) {
        const int pos = t * 4 + nc;
        const int r0 = m0 + wm + tm * 16 + g;
        uint32_t h, l;
        {
          const int b = r0 >> 10, s = r0 & 1023;
          split2(c[tm][nc][0], c[tm][nc][1], h, l);
          const size_t o = ((size_t)(b * kH + head) * kS + s) * 16 + pos;
          outh[o] = h; outl[o] = l;
        }
        {
          const int r1 = r0 + 8;
          const int b = r1 >> 10, s = r1 & 1023;
          split2(c[tm][nc][2], c[tm][nc][3], h, l);
          const size_t o = ((size_t)(b * kH + head) * kS + s) * 16 + pos;
          outh[o] = h; outl[o] = l;
        }
      }
  } else {
#pragma unroll
    for (int tm = 0; tm < 2; tm++)
#pragma unroll
      for (int nc = 0; nc < 4; nc++)
#pragma unroll
        for (int hh = 0; hh < 2; hh++) {
          float v0 = c[tm][nc][hh * 2];
          float v1 = c[tm][nc][hh * 2 + 1];
          float v0o = __shfl_down_sync(0xffffffffu, v0, 4);
          float v1o = __shfl_down_sync(0xffffffffu, v1, 4);
          if ((g & 1) == 0) {
            const int m = m0 + wm + tm * 16 + g + hh * 8;
            const int b = m >> 10, s = m & 1023;
            const int kt = s >> 7;
            const int jp = (s & 127) >> 1;
            const int pos = (jp & ~7) + ((jp & 3) << 1) + ((jp >> 2) & 1);
            const int d = nc * 8 + 2 * t;
            const size_t base = ((size_t)(b * kH + head) * 8 + kt) * kD;
            uint32_t h0, l0, h1, l1;
            split2(v0, v0o, h0, l0);
            split2(v1, v1o, h1, l1);
            g_vth[(base + d) * 64 + pos] = h0;
            g_vtl[(base + d) * 64 + pos] = l0;
            g_vth[(base + d + 1) * 64 + pos] = h1;
            g_vtl[(base + d + 1) * 64 + pos] = l1;
          }
        }
  }
}

// ---------------------------------------------------------------------------
// Fused attention, R15: cp.async double-buffered K tiles, V streamed global.
// ---------------------------------------------------------------------------
__device__ __forceinline__ void score6(float* c,
                                       const uint32_t aqh[2][4],
                                       const uint32_t aql[2][4],
                                       const uint32_t* __restrict__ Kh,
                                       const uint32_t* __restrict__ Kl,
                                       int rb) {
  uint4 fh = *(const uint4*)&Kh[rb];
  uint4 fl = *(const uint4*)&Kl[rb];
  c[0] = c[1] = c[2] = c[3] = 0.f;
  mma_bf16(c, aqh[0], fh.x, fh.y);
  mma_bf16(c, aqh[0], fl.x, fl.y);
  mma_bf16(c, aql[0], fh.x, fh.y);
  mma_bf16(c, aqh[1], fh.z, fh.w);
  mma_bf16(c, aqh[1], fl.z, fl.w);
  mma_bf16(c, aql[1], fh.z, fh.w);
}

__global__ __launch_bounds__(256, 3) void attn_kernel(
    const float* __restrict__ mask, const float* __restrict__ pi,
    float* __restrict__ out_ctx, float* __restrict__ out_probs)
{
  extern __shared__ uint32_t su[];
  float* colc1 = (float*)(su + U_COLC1);
  float* colc2 = (float*)(su + U_COLC2);
  uint32_t* bufp[2] = {su + U_BUF0, su + U_BUF1};

  const int tid = threadIdx.x;
  const int w = tid >> 5, lane = tid & 31;
  const int g = lane >> 2, t = lane & 3;
  const int R0 = w * 16 + g, R1 = R0 + 8;

  const int qt = blockIdx.x, bh = blockIdx.y;
  const int b = bh / kH, h = bh % kH;
  const int q0 = qt * 128;
  const int nbase = bh * kS;
  const size_t gbase = (size_t)bh * kS * kD;

  const float pi0 = fminf(fmaxf(pi[h],      1e-6f), 2.0f);
  const float pi1 = fminf(fmaxf(pi[kH + h], 1e-6f), 2.0f);
  const float lp0 = __log2f(pi0), lp1 = __log2f(pi1);

  // buffer smem byte addresses for cp.async
  const uint32_t bufaddr0 = smem_addr_of(su) + U_BUF0 * 4;
  const uint32_t bufaddr1 = smem_addr_of(su) + U_BUF1 * 4;

  // issue K tile j0 into buffer (8 cp.async/thread, one commit group)
#define ISSUE_K(j0, baddr)                                                    \
  {                                                                           \
    const size_t gw = (size_t)(nbase + (j0)) * 16;                            \
    uint32_t sa = (baddr) + tid * 16;                                         \
    _Pragma("unroll")                                                         \
    for (int i = tid * 4; i < 2048; i += 1024, sa += 4096) {                  \
      cp_async16(sa,         &g_k1h[gw + i]);                                 \
      cp_async16(sa + 8192,  &g_k1l[gw + i]);                                 \
      cp_async16(sa + 16384, &g_k2h[gw + i]);                                 \
      cp_async16(sa + 24576, &g_k2l[gw + i]);                                 \
    }                                                                         \
    cp_commit();                                                              \
  }

  // ---- stage colc tables + Q (Q stage aliases BUF1) ----
  for (int i = tid; i < kS; i += 256) {
    const float mk = mask[b * kS + i] * kLog2e;
    colc1[i] = fmaf(-kC1L, g_nk1[nbase + i], mk);
    colc2[i] = fmaf(-kC2L, g_nk2[nbase + i], mk);
  }
  {
    float* qst = (float*)bufp[1];   // [128][33]
    for (int i = tid; i < 1024; i += 256) {
      const int j = i >> 3, dg = (i & 7) * 4;
      float4 v = *(const float4*)&g_q[gbase + (size_t)(q0 + j) * kD + dg];
      qst[j * 33 + dg + 0] = v.x; qst[j * 33 + dg + 1] = v.y;
      qst[j * 33 + dg + 2] = v.z; qst[j * 33 + dg + 3] = v.w;
    }
  }
  ISSUE_K(0, bufaddr0)             // prologue: kt=0 -> buf0 (disjoint region)
  __syncthreads();

  uint32_t aqh[2][4], aql[2][4];
  {
    float* qst = (float*)bufp[1];
#pragma unroll
    for (int ks = 0; ks < 2; ks++) {
      const int d0 = 16 * ks + 2 * t;
      split2(qst[R0 * 33 + d0],     qst[R0 * 33 + d0 + 1], aqh[ks][0], aql[ks][0]);
      split2(qst[R1 * 33 + d0],     qst[R1 * 33 + d0 + 1], aqh[ks][1], aql[ks][1]);
      split2(qst[R0 * 33 + d0 + 8], qst[R0 * 33 + d0 + 9], aqh[ks][2], aql[ks][2]);
      split2(qst[R1 * 33 + d0 + 8], qst[R1 * 33 + d0 + 9], aqh[ks][3], aql[ks][3]);
    }
  }
  const float nq0 = g_nq[nbase + q0 + R0];
  const float nq1 = g_nq[nbase + q0 + R1];
  const float rq1a = -kC1L * nq0, rq1b = -kC1L * nq1;
  const float rq2a = -kC2L * nq0, rq2b = -kC2L * nq1;
  __syncthreads();                 // done with BUF1 (qst) before kt=0 issues kt1

  // ====== pass 1: exact maxes + fixed-reference rowsums ======
  float m1a = -1e30f, m1b = -1e30f, m2a = -1e30f, m2b = -1e30f;
  float l1a = 0.f, l1b = 0.f, l2a = 0.f, l2b = 0.f;

  for (int kt = 0; kt < 8; kt++) {
    const uint32_t* cb = bufp[kt & 1];
    if (kt < 7) {
      ISSUE_K((kt + 1) * 128, (kt & 1) ? bufaddr0 : bufaddr1)
      cp_wait1();
    } else {
      cp_wait0();
    }
    __syncthreads();
    const uint32_t* Kh1 = cb, *Kl1 = cb + 2048, *Kh2 = cb + 4096, *Kl2 = cb + 6144;
#pragma unroll 2
    for (int nt = 0; nt < 16; nt++) {
      const int rb = ((nt * 8 + g) << 4) + t * 4;
      const int col = kt * 128 + nt * 8 + 2 * t;
      const float2 cc1 = *(const float2*)&colc1[col];
      const float2 cc2 = *(const float2*)&colc2[col];
      float c1[4], c2[4];
      score6(c1, aqh, aql, Kh1, Kl1, rb);
      score6(c2, aqh, aql, Kh2, Kl2, rb);
      {
        float s0 = fmaf(kTC1, c1[0], cc1.x + rq1a);
        float s1 = fmaf(kTC1, c1[1], cc1.y + rq1a);
        m1a = fmaxf(m1a, fmaxf(s0, s1));
        l1a += ex2(s0) + ex2(s1);
      }
      {
        float s0 = fmaf(kTC1, c1[2], cc1.x + rq1b);
        float s1 = fmaf(kTC1, c1[3], cc1.y + rq1b);
        m1b = fmaxf(m1b, fmaxf(s0, s1));
        l1b += ex2(s0) + ex2(s1);
      }
      {
        float s0 = fmaf(kTC2, c2[0], cc2.x + rq2a);
        float s1 = fmaf(kTC2, c2[1], cc2.y + rq2a);
        m2a = fmaxf(m2a, fmaxf(s0, s1));
        l2a += ex2(s0) + ex2(s1);
      }
      {
        float s0 = fmaf(kTC2, c2[2], cc2.x + rq2b);
        float s1 = fmaf(kTC2, c2[3], cc2.y + rq2b);
        m2b = fmaxf(m2b, fmaxf(s0, s1));
        l2b += ex2(s0) + ex2(s1);
      }
    }
    __syncthreads();   // all reads of cb done before it is refilled at kt+2
  }
#pragma unroll
  for (int o = 1; o < 4; o <<= 1) {
    m1a = fmaxf(m1a, __shfl_xor_sync(0xffffffffu, m1a, o));
    m1b = fmaxf(m1b, __shfl_xor_sync(0xffffffffu, m1b, o));
    m2a = fmaxf(m2a, __shfl_xor_sync(0xffffffffu, m2a, o));
    m2b = fmaxf(m2b, __shfl_xor_sync(0xffffffffu, m2b, o));
    l1a += __shfl_xor_sync(0xffffffffu, l1a, o);
    l1b += __shfl_xor_sync(0xffffffffu, l1b, o);
    l2a += __shfl_xor_sync(0xffffffffu, l2a, o);
    l2b += __shfl_xor_sync(0xffffffffu, l2b, o);
  }
  const float inv0 = 1.0f / (pi0 * ex2(-m1a) * l1a +
                             pi1 * ex2(-m2a) * l2a + 1e-6f);
  const float inv1 = 1.0f / (pi0 * ex2(-m1b) * l1b +
                             pi1 * ex2(-m2b) * l2b + 1e-6f);
  const float rq1a2 = rq1a + lp0 - m1a, rq1b2 = rq1b + lp0 - m1b;
  const float rq2a2 = rq2a + lp1 - m2a, rq2b2 = rq2b + lp1 - m2b;

  // ====== pass 2: probs + E@V (V streamed from global) ======
  float cctx[4][4];
#pragma unroll
  for (int i = 0; i < 4; i++)
#pragma unroll
    for (int j = 0; j < 4; j++) cctx[i][j] = 0.f;

  uint32_t eh[4], el[4];

  ISSUE_K(0, bufaddr0)             // pass-2 prologue (buffers drained above)

  for (int kt = 0; kt < 8; kt++) {
    const uint32_t* cb = bufp[kt & 1];
    if (kt < 7) {
      ISSUE_K((kt + 1) * 128, (kt & 1) ? bufaddr0 : bufaddr1)
      cp_wait1();
    } else {
      cp_wait0();
    }
    __syncthreads();
    const uint32_t* Kh1 = cb, *Kl1 = cb + 2048, *Kh2 = cb + 4096, *Kl2 = cb + 6144;
    const size_t vg = ((size_t)bh * 8 + kt) * (kD * 64);
#pragma unroll 2
    for (int nt = 0; nt < 16; nt++) {
      const int rb = ((nt * 8 + g) << 4) + t * 4;
      const int col = kt * 128 + nt * 8 + 2 * t;
      const float2 cc1 = *(const float2*)&colc1[col];
      const float2 cc2 = *(const float2*)&colc2[col];
      float c1[4], c2[4];
      score6(c1, aqh, aql, Kh1, Kl1, rb);
      score6(c2, aqh, aql, Kh2, Kl2, rb);
      float p00 = (ex2(fmaf(kTC1, c1[0], cc1.x + rq1a2))
                 + ex2(fmaf(kTC2, c2[0], cc2.x + rq2a2))) * inv0;
      float p01 = (ex2(fmaf(kTC1, c1[1], cc1.y + rq1a2))
                 + ex2(fmaf(kTC2, c2[1], cc2.y + rq2a2))) * inv0;
      float p10 = (ex2(fmaf(kTC1, c1[2], cc1.x + rq1b2))
                 + ex2(fmaf(kTC2, c2[2], cc2.x + rq2b2))) * inv1;
      float p11 = (ex2(fmaf(kTC1, c1[3], cc1.y + rq1b2))
                 + ex2(fmaf(kTC2, c2[3], cc2.y + rq2b2))) * inv1;

      const size_t pb = ((size_t)bh * kS + q0 + R0) * kS + col;
      __stcs((float2*)&out_probs[pb], make_float2(p00, p01));
      __stcs((float2*)&out_probs[pb + 8 * kS], make_float2(p10, p11));

      if ((nt & 1) == 0) {
        split2(p00, p01, eh[0], el[0]);
        split2(p10, p11, eh[1], el[1]);
      } else {
        split2(p00, p01, eh[2], el[2]);
        split2(p10, p11, eh[3], el[3]);
        const int ks = nt >> 1;
#pragma unroll
        for (int nd = 0; nd < 4; nd++) {
          const size_t vb = vg + (size_t)(nd * 8 + g) * 64 + 8 * ks + 2 * t;
          uint2 vh = *(const uint2*)&g_vth[vb];
          uint2 vl = *(const uint2*)&g_vtl[vb];
          mma_bf16(cctx[nd], eh, vh.x, vh.y);
          mma_bf16(cctx[nd], eh, vl.x, vl.y);
          mma_bf16(cctx[nd], el, vh.x, vh.y);
        }
      }
    }
    __syncthreads();
  }

#pragma unroll
  for (int nd = 0; nd < 4; nd++) {
    const int d = nd * 8 + 2 * t;
    *(float2*)&out_ctx[((size_t)b * kS + q0 + R0) * kAH + h * kD + d] =
        make_float2(cctx[nd][0], cctx[nd][1]);
    *(float2*)&out_ctx[((size_t)b * kS + q0 + R1) * kAH + h * kD + d] =
        make_float2(cctx[nd][2], cctx[nd][3]);
  }
#undef ISSUE_K
}

// ---------------------------------------------------------------------------
extern "C" void kernel_launch(void* const* d_in, const int* in_sizes, int n_in,
                              void* d_out, int out_size) {
  (void)in_sizes; (void)n_in; (void)out_size;
  const float* hs   = (const float*)d_in[0];
  const float* mask = (const float*)d_in[1];
  const float* Wq   = (const float*)d_in[2];
  const float* bq   = (const float*)d_in[3];
  const float* Wk1  = (const float*)d_in[4];
  const float* bk1  = (const float*)d_in[5];
  const float* Wk2  = (const float*)d_in[6];
  const float* bk2  = (const float*)d_in[7];
  const float* Wv   = (const float*)d_in[8];
  const float* bv   = (const float*)d_in[9];
  const float* pi   = (const float*)d_in[10];

  float* out_ctx   = (float*)d_out;
  float* out_probs = out_ctx + (size_t)kB * kS * kAH;

  cudaFuncSetAttribute(attn_kernel, cudaFuncAttributeMaxDynamicSharedMemorySize,
                       kAttnSmemBytes);

  const int total_warps = kMB * kKC + 4 * kNB * kKC;
  presplit_kernel<<<(total_warps + 7) / 8, 256>>>(hs, Wq, Wk1, Wk2, Wv);

  dim3 pgrid(kAH / 64, (kB * kS) / 128, 4);   // (6, 32, 4) = 768 CTAs
  proj_kernel<<<pgrid, 256>>>(bq, bk1, bk2, bv);
  attn_kernel<<<dim3(kS / 128, kBH), 256, kAttnSmemBytes>>>(
      mask, pi, out_ctx, out_probs);
}

// round 16
// speedup vs baseline: 1.0872x; 1.0323x over previous
#include <cuda_runtime.h>
#include <cuda_bf16.h>
#include <cstdint>

// ---------------------------------------------------------------------------
// MGKBertSelfAttention: B=4, S=1024, HID=768, H=12, D=32, AH=384
// out = [ctx (B,S,AH) ; probs (B,H,S,S)]  fp32
// mma.sync m16n8k16 bf16, 2-term hi/lo split (3-product, fp32-equiv precision).
// R16: exact R12 base (best) + proj 2-stage register-prefetch pipeline.
// ---------------------------------------------------------------------------

namespace {
constexpr int kB = 4, kS = 1024, kHid = 768, kH = 12, kD = 32, kAH = 384;
constexpr int kBH = kB * kH;                       // 48
constexpr float kScaling = 0.17677669529663687f;   // 32^-0.5
constexpr float kC1 = 0.5f * kScaling;
constexpr float kC2 = 0.75f * kScaling;
constexpr float kLog2e = 1.4426950408889634f;
constexpr float kC1L = kC1 * kLog2e;
constexpr float kC2L = kC2 * kLog2e;
constexpr float kTC1 = 2.0f * kC1L;
constexpr float kTC2 = 2.0f * kC2L;

constexpr int kMB = (kB * kS) / 16;   // 256 m-blocks (16 rows)
constexpr int kKC = kHid / 16;        // 48 k-chunks
constexpr int kNB = kAH / 8;          // 48 n-blocks (8 cols)

// attn smem layout (u32 units) — identical to R12
constexpr int U_COLC1 = 0;
constexpr int U_COLC2 = 1024;
constexpr int U_K1H   = 2048;
constexpr int U_K1L   = U_K1H + 2048;
constexpr int U_K2H   = U_K1L + 2048;
constexpr int U_K2L   = U_K2H + 2048;
constexpr int U_VTH   = U_K2L + 2048;
constexpr int U_VTL   = U_VTH + 2304;
constexpr int kAttnSmemU32 = U_VTL + 2304;
constexpr int kAttnSmemBytes = kAttnSmemU32 * 4;    // 59648 B
}

// Scratch (device globals; allocation is forbidden)
__device__ float    g_q  [kBH * kS * kD];
__device__ uint32_t g_k1h[kBH * kS * 16];
__device__ uint32_t g_k1l[kBH * kS * 16];
__device__ uint32_t g_k2h[kBH * kS * 16];
__device__ uint32_t g_k2l[kBH * kS * 16];
__device__ uint32_t g_vth[kBH * 8 * kD * 64];
__device__ uint32_t g_vtl[kBH * 8 * kD * 64];
__device__ float    g_nq [kBH * kS];
__device__ float    g_nk1[kBH * kS];
__device__ float    g_nk2[kBH * kS];
// fragment-major pre-split operands
__device__ uint32_t g_xfh[kMB * kKC * 32 * 4];
__device__ uint32_t g_xfl[kMB * kKC * 32 * 4];
__device__ uint32_t g_wfh[4 * kNB * kKC * 32 * 2];
__device__ uint32_t g_wfl[4 * kNB * kKC * 32 * 2];

// ---------------------------------------------------------------------------
// helpers
// ---------------------------------------------------------------------------
__device__ __forceinline__ float ex2(float x) {
  float r;
  asm("ex2.approx.f32 %0, %1;" : "=f"(r) : "f"(x));
  return r;
}
__device__ __forceinline__ void split2(float x, float y, uint32_t& h, uint32_t& l) {
  __nv_bfloat16 bx = __float2bfloat16_rn(x);
  __nv_bfloat16 by = __float2bfloat16_rn(y);
  float rx = x - __bfloat162float(bx);
  float ry = y - __bfloat162float(by);
  __nv_bfloat16 lx = __float2bfloat16_rn(rx);
  __nv_bfloat16 ly = __float2bfloat16_rn(ry);
  h = (uint32_t)__bfloat16_as_ushort(bx) | ((uint32_t)__bfloat16_as_ushort(by) << 16);
  l = (uint32_t)__bfloat16_as_ushort(lx) | ((uint32_t)__bfloat16_as_ushort(ly) << 16);
}
__device__ __forceinline__ void mma_bf16(float* c, const uint32_t* a,
                                         uint32_t b0, uint32_t b1) {
  asm volatile(
      "mma.sync.aligned.m16n8k16.row.col.f32.bf16.bf16.f32 "
      "{%0,%1,%2,%3}, {%4,%5,%6,%7}, {%8,%9}, {%0,%1,%2,%3};\n"
      : "+f"(c[0]), "+f"(c[1]), "+f"(c[2]), "+f"(c[3])
      : "r"(a[0]), "r"(a[1]), "r"(a[2]), "r"(a[3]), "r"(b0), "r"(b1));
}

// ---------------------------------------------------------------------------
// Pre-split kernel (unchanged from R12)
// ---------------------------------------------------------------------------
__global__ __launch_bounds__(256) void presplit_kernel(
    const float* __restrict__ X,
    const float* __restrict__ Wq, const float* __restrict__ Wk1,
    const float* __restrict__ Wk2, const float* __restrict__ Wv)
{
  const int wg = blockIdx.x * 8 + (threadIdx.x >> 5);
  const int lane = threadIdx.x & 31;
  const int g = lane >> 2, t = lane & 3;

  if (wg < kMB * kKC) {
    const int mb = wg / kKC, kc = wg % kKC;
    const float* p0 = X + (size_t)(mb * 16 + g) * kHid + kc * 16 + 2 * t;
    const float* p1 = p0 + 8 * kHid;
    float2 v00 = *(const float2*)p0;
    float2 v01 = *(const float2*)(p0 + 8);
    float2 v10 = *(const float2*)p1;
    float2 v11 = *(const float2*)(p1 + 8);
    uint4 hv, lv;
    split2(v00.x, v00.y, hv.x, lv.x);
    split2(v10.x, v10.y, hv.y, lv.y);
    split2(v01.x, v01.y, hv.z, lv.z);
    split2(v11.x, v11.y, hv.w, lv.w);
    const size_t o = ((size_t)wg * 32 + lane) * 4;
    *(uint4*)&g_xfh[o] = hv;
    *(uint4*)&g_xfl[o] = lv;
  } else {
    const int r = wg - kMB * kKC;
    if (r >= 4 * kNB * kKC) return;
    const int sel = r / (kNB * kKC);
    const int rr = r % (kNB * kKC);
    const int nb = rr / kKC, kc = rr % kKC;
    const float* W = (sel == 0) ? Wq : (sel == 1) ? Wk1 : (sel == 2) ? Wk2 : Wv;
    const float* p = W + (size_t)(nb * 8 + g) * kHid + kc * 16 + 2 * t;
    float2 v0 = *(const float2*)p;
    float2 v1 = *(const float2*)(p + 8);
    uint32_t h0, l0, h1, l1;
    split2(v0.x, v0.y, h0, l0);
    split2(v1.x, v1.y, h1, l1);
    const size_t o = ((size_t)r * 32 + lane) * 2;
    g_wfh[o] = h0; g_wfh[o + 1] = h1;
    g_wfl[o] = l0; g_wfl[o + 1] = l1;
  }
}

// ---------------------------------------------------------------------------
// Streaming projection GEMM, R16: 2-stage register prefetch pipeline.
// ---------------------------------------------------------------------------
__global__ __launch_bounds__(256, 2) void proj_kernel(
    const float* __restrict__ bq, const float* __restrict__ bk1,
    const float* __restrict__ bk2, const float* __restrict__ bv)
{
  const int sel = blockIdx.z;
  const float* bias = (sel == 0) ? bq : (sel == 1) ? bk1 : (sel == 2) ? bk2 : bv;

  const int tid = threadIdx.x;
  const int w = tid >> 5, lane = tid & 31;
  const int g = lane >> 2, t = lane & 3;
  const int wm = (w & 3) * 32, wn = (w >> 2) * 32;
  const int m0 = blockIdx.y * 128, n0 = blockIdx.x * 64;

  const int mb0 = (m0 + wm) >> 4;
  const int nb0 = (n0 + wn) >> 3;
  const size_t xbase0 = (((size_t)mb0 * kKC) * 32 + lane) * 4;
  const size_t xbase1 = ((((size_t)mb0 + 1) * kKC) * 32 + lane) * 4;
  const size_t wsel = (size_t)sel * kNB * kKC * 64;
  size_t wbase[4];
#pragma unroll
  for (int nc = 0; nc < 4; nc++)
    wbase[nc] = wsel + (((size_t)(nb0 + nc) * kKC) * 32 + lane) * 2;

  float c[2][4][4];
#pragma unroll
  for (int i = 0; i < 2; i++)
#pragma unroll
    for (int j = 0; j < 4; j++)
#pragma unroll
      for (int k = 0; k < 4; k++) c[i][j][k] = 0.f;

  // double-buffered fragment registers
  uint4 ah[2][2], al[2][2];
  uint2 bh[2][4], bl[2][4];

#define LOAD_FRAGS(buf, kc)                                                   \
  {                                                                           \
    ah[buf][0] = *(const uint4*)&g_xfh[xbase0 + (size_t)(kc) * 128];          \
    al[buf][0] = *(const uint4*)&g_xfl[xbase0 + (size_t)(kc) * 128];          \
    ah[buf][1] = *(const uint4*)&g_xfh[xbase1 + (size_t)(kc) * 128];          \
    al[buf][1] = *(const uint4*)&g_xfl[xbase1 + (size_t)(kc) * 128];          \
    _Pragma("unroll")                                                         \
    for (int nc = 0; nc < 4; nc++) {                                          \
      const size_t wo = wbase[nc] + (size_t)(kc) * 64;                        \
      bh[buf][nc] = *(const uint2*)&g_wfh[wo];                                \
      bl[buf][nc] = *(const uint2*)&g_wfl[wo];                                \
    }                                                                         \
  }

#define DO_MMAS(buf)                                                          \
  {                                                                           \
    _Pragma("unroll")                                                         \
    for (int nc = 0; nc < 4; nc++) {                                          \
      _Pragma("unroll")                                                       \
      for (int tm = 0; tm < 2; tm++) {                                        \
        mma_bf16(c[tm][nc], (const uint32_t*)&ah[buf][tm],                    \
                 bh[buf][nc].x, bh[buf][nc].y);                               \
        mma_bf16(c[tm][nc], (const uint32_t*)&ah[buf][tm],                    \
                 bl[buf][nc].x, bl[buf][nc].y);                               \
        mma_bf16(c[tm][nc], (const uint32_t*)&al[buf][tm],                    \
                 bh[buf][nc].x, bh[buf][nc].y);                               \
      }                                                                       \
    }                                                                         \
  }

  LOAD_FRAGS(0, 0)
#pragma unroll 4
  for (int kc = 0; kc < kKC; kc += 2) {
    LOAD_FRAGS(1, kc + 1)
    DO_MMAS(0)
    if (kc + 2 < kKC) LOAD_FRAGS(0, kc + 2)
    DO_MMAS(1)
  }
#undef LOAD_FRAGS
#undef DO_MMAS

  const int head = (n0 + wn) >> 5;
#pragma unroll
  for (int nc = 0; nc < 4; nc++) {
    const float bb0 = bias[n0 + wn + nc * 8 + 2 * t];
    const float bb1 = bias[n0 + wn + nc * 8 + 2 * t + 1];
#pragma unroll
    for (int tm = 0; tm < 2; tm++) {
      c[tm][nc][0] += bb0; c[tm][nc][1] += bb1;
      c[tm][nc][2] += bb0; c[tm][nc][3] += bb1;
    }
  }

  if (sel < 3) {
    float* nrm = (sel == 0) ? g_nq : (sel == 1) ? g_nk1 : g_nk2;
    float ps[2][2] = {{0.f, 0.f}, {0.f, 0.f}};
#pragma unroll
    for (int tm = 0; tm < 2; tm++)
#pragma unroll
      for (int nc = 0; nc < 4; nc++) {
        ps[tm][0] = fmaf(c[tm][nc][0], c[tm][nc][0],
                    fmaf(c[tm][nc][1], c[tm][nc][1], ps[tm][0]));
        ps[tm][1] = fmaf(c[tm][nc][2], c[tm][nc][2],
                    fmaf(c[tm][nc][3], c[tm][nc][3], ps[tm][1]));
      }
#pragma unroll
    for (int tm = 0; tm < 2; tm++)
#pragma unroll
      for (int hh = 0; hh < 2; hh++) {
#pragma unroll
        for (int o = 1; o < 4; o <<= 1)
          ps[tm][hh] += __shfl_xor_sync(0xffffffffu, ps[tm][hh], o);
      }
    if (t == 0) {
#pragma unroll
      for (int tm = 0; tm < 2; tm++)
#pragma unroll
        for (int hh = 0; hh < 2; hh++) {
          const int r = m0 + wm + tm * 16 + g + hh * 8;
          const int b = r >> 10, s = r & 1023;
          nrm[(b * kH + head) * kS + s] = ps[tm][hh];
        }
    }
  }

  if (sel == 0) {
#pragma unroll
    for (int tm = 0; tm < 2; tm++)
#pragma unroll
      for (int nc = 0; nc < 4; nc++) {
        const int d = nc * 8 + 2 * t;
        const int r0 = m0 + wm + tm * 16 + g;
        {
          const int b = r0 >> 10, s = r0 & 1023;
          *(float2*)&g_q[(((size_t)b * kH + head) * kS + s) * kD + d] =
              make_float2(c[tm][nc][0], c[tm][nc][1]);
        }
        {
          const int r1 = r0 + 8;
          const int b = r1 >> 10, s = r1 & 1023;
          *(float2*)&g_q[(((size_t)b * kH + head) * kS + s) * kD + d] =
              make_float2(c[tm][nc][2], c[tm][nc][3]);
        }
      }
  } else if (sel < 3) {
    uint32_t* outh = (sel == 1) ? g_k1h : g_k2h;
    uint32_t* outl = (sel == 1) ? g_k1l : g_k2l;
#pragma unroll
    for (int tm = 0; tm < 2; tm++)
#pragma unroll
      for (int nc = 0; nc < 4; nc++) {
        const int pos = t * 4 + nc;
        const int r0 = m0 + wm + tm * 16 + g;
        uint32_t h, l;
        {
          const int b = r0 >> 10, s = r0 & 1023;
          split2(c[tm][nc][0], c[tm][nc][1], h, l);
          const size_t o = ((size_t)(b * kH + head) * kS + s) * 16 + pos;
          outh[o] = h; outl[o] = l;
        }
        {
          const int r1 = r0 + 8;
          const int b = r1 >> 10, s = r1 & 1023;
          split2(c[tm][nc][2], c[tm][nc][3], h, l);
          const size_t o = ((size_t)(b * kH + head) * kS + s) * 16 + pos;
          outh[o] = h; outl[o] = l;
        }
      }
  } else {
#pragma unroll
    for (int tm = 0; tm < 2; tm++)
#pragma unroll
      for (int nc = 0; nc < 4; nc++)
#pragma unroll
        for (int hh = 0; hh < 2; hh++) {
          float v0 = c[tm][nc][hh * 2];
          float v1 = c[tm][nc][hh * 2 + 1];
          float v0o = __shfl_down_sync(0xffffffffu, v0, 4);
          float v1o = __shfl_down_sync(0xffffffffu, v1, 4);
          if ((g & 1) == 0) {
            const int m = m0 + wm + tm * 16 + g + hh * 8;
            const int b = m >> 10, s = m & 1023;
            const int kt = s >> 7;
            const int jp = (s & 127) >> 1;
            const int pos = (jp & ~7) + ((jp & 3) << 1) + ((jp >> 2) & 1);
            const int d = nc * 8 + 2 * t;
            const size_t base = ((size_t)(b * kH + head) * 8 + kt) * kD;
            uint32_t h0, l0, h1, l1;
            split2(v0, v0o, h0, l0);
            split2(v1, v1o, h1, l1);
            g_vth[(base + d) * 64 + pos] = h0;
            g_vtl[(base + d) * 64 + pos] = l0;
            g_vth[(base + d + 1) * 64 + pos] = h1;
            g_vtl[(base + d + 1) * 64 + pos] = l1;
          }
        }
  }
}

// ---------------------------------------------------------------------------
// Fused attention (byte-identical to R12).
// ---------------------------------------------------------------------------
__device__ __forceinline__ void score6(float* c,
                                       const uint32_t aqh[2][4],
                                       const uint32_t aql[2][4],
                                       const uint32_t* __restrict__ Kh,
                                       const uint32_t* __restrict__ Kl,
                                       int rb) {
  uint4 fh = *(const uint4*)&Kh[rb];
  uint4 fl = *(const uint4*)&Kl[rb];
  c[0] = c[1] = c[2] = c[3] = 0.f;
  mma_bf16(c, aqh[0], fh.x, fh.y);
  mma_bf16(c, aqh[0], fl.x, fl.y);
  mma_bf16(c, aql[0], fh.x, fh.y);
  mma_bf16(c, aqh[1], fh.z, fh.w);
  mma_bf16(c, aqh[1], fl.z, fl.w);
  mma_bf16(c, aql[1], fh.z, fh.w);
}

__global__ __launch_bounds__(256, 3) void attn_kernel(
    const float* __restrict__ mask, const float* __restrict__ pi,
    float* __restrict__ out_ctx, float* __restrict__ out_probs)
{
  extern __shared__ uint32_t su[];
  float* colc1 = (float*)(su + U_COLC1);
  float* colc2 = (float*)(su + U_COLC2);
  uint32_t* K1h = su + U_K1H;
  uint32_t* K1l = su + U_K1L;
  uint32_t* K2h = su + U_K2H;
  uint32_t* K2l = su + U_K2L;
  uint32_t* Vth = su + U_VTH;
  uint32_t* Vtl = su + U_VTL;

  const int tid = threadIdx.x;
  const int w = tid >> 5, lane = tid & 31;
  const int g = lane >> 2, t = lane & 3;
  const int R0 = w * 16 + g, R1 = R0 + 8;

  const int qt = blockIdx.x, bh = blockIdx.y;
  const int b = bh / kH, h = bh % kH;
  const int q0 = qt * 128;
  const int nbase = bh * kS;
  const size_t gbase = (size_t)bh * kS * kD;

  const float pi0 = fminf(fmaxf(pi[h],      1e-6f), 2.0f);
  const float pi1 = fminf(fmaxf(pi[kH + h], 1e-6f), 2.0f);
  const float lp0 = __log2f(pi0), lp1 = __log2f(pi1);

  for (int i = tid; i < kS; i += 256) {
    const float mk = mask[b * kS + i] * kLog2e;
    colc1[i] = fmaf(-kC1L, g_nk1[nbase + i], mk);
    colc2[i] = fmaf(-kC2L, g_nk2[nbase + i], mk);
  }

  {
    float* qst = (float*)(su + U_K1H);
    for (int i = tid; i < 1024; i += 256) {
      const int j = i >> 3, dg = (i & 7) * 4;
      float4 v = *(const float4*)&g_q[gbase + (size_t)(q0 + j) * kD + dg];
      qst[j * 33 + dg + 0] = v.x; qst[j * 33 + dg + 1] = v.y;
      qst[j * 33 + dg + 2] = v.z; qst[j * 33 + dg + 3] = v.w;
    }
  }
  __syncthreads();

  uint32_t aqh[2][4], aql[2][4];
  {
    float* qst = (float*)(su + U_K1H);
#pragma unroll
    for (int ks = 0; ks < 2; ks++) {
      const int d0 = 16 * ks + 2 * t;
      split2(qst[R0 * 33 + d0],     qst[R0 * 33 + d0 + 1], aqh[ks][0], aql[ks][0]);
      split2(qst[R1 * 33 + d0],     qst[R1 * 33 + d0 + 1], aqh[ks][1], aql[ks][1]);
      split2(qst[R0 * 33 + d0 + 8], qst[R0 * 33 + d0 + 9], aqh[ks][2], aql[ks][2]);
      split2(qst[R1 * 33 + d0 + 8], qst[R1 * 33 + d0 + 9], aqh[ks][3], aql[ks][3]);
    }
  }
  const float nq0 = g_nq[nbase + q0 + R0];
  const float nq1 = g_nq[nbase + q0 + R1];
  const float rq1a = -kC1L * nq0, rq1b = -kC1L * nq1;
  const float rq2a = -kC2L * nq0, rq2b = -kC2L * nq1;
  __syncthreads();

#define LOAD_K(j0)                                                            \
  {                                                                           \
    const size_t gw = (size_t)(nbase + (j0)) * 16;                            \
    for (int i = tid * 4; i < 2048; i += 1024) {                              \
      *(uint4*)&K1h[i] = *(const uint4*)&g_k1h[gw + i];                       \
      *(uint4*)&K1l[i] = *(const uint4*)&g_k1l[gw + i];                       \
      *(uint4*)&K2h[i] = *(const uint4*)&g_k2h[gw + i];                       \
      *(uint4*)&K2l[i] = *(const uint4*)&g_k2l[gw + i];                       \
    }                                                                         \
  }

  // ====== pass 1 ======
  float m1a = -1e30f, m1b = -1e30f, m2a = -1e30f, m2b = -1e30f;
  float l1a = 0.f, l1b = 0.f, l2a = 0.f, l2b = 0.f;

  for (int kt = 0; kt < 8; kt++) {
    __syncthreads();
    LOAD_K(kt * 128)
    __syncthreads();
#pragma unroll 2
    for (int nt = 0; nt < 16; nt++) {
      const int rb = ((nt * 8 + g) << 4) + t * 4;
      const int col = kt * 128 + nt * 8 + 2 * t;
      const float2 cc1 = *(const float2*)&colc1[col];
      const float2 cc2 = *(const float2*)&colc2[col];
      float c1[4], c2[4];
      score6(c1, aqh, aql, K1h, K1l, rb);
      score6(c2, aqh, aql, K2h, K2l, rb);
      {
        float s0 = fmaf(kTC1, c1[0], cc1.x + rq1a);
        float s1 = fmaf(kTC1, c1[1], cc1.y + rq1a);
        m1a = fmaxf(m1a, fmaxf(s0, s1));
        l1a += ex2(s0) + ex2(s1);
      }
      {
        float s0 = fmaf(kTC1, c1[2], cc1.x + rq1b);
        float s1 = fmaf(kTC1, c1[3], cc1.y + rq1b);
        m1b = fmaxf(m1b, fmaxf(s0, s1));
        l1b += ex2(s0) + ex2(s1);
      }
      {
        float s0 = fmaf(kTC2, c2[0], cc2.x + rq2a);
        float s1 = fmaf(kTC2, c2[1], cc2.y + rq2a);
        m2a = fmaxf(m2a, fmaxf(s0, s1));
        l2a += ex2(s0) + ex2(s1);
      }
      {
        float s0 = fmaf(kTC2, c2[2], cc2.x + rq2b);
        float s1 = fmaf(kTC2, c2[3], cc2.y + rq2b);
        m2b = fmaxf(m2b, fmaxf(s0, s1));
        l2b += ex2(s0) + ex2(s1);
      }
    }
  }
#pragma unroll
  for (int o = 1; o < 4; o <<= 1) {
    m1a = fmaxf(m1a, __shfl_xor_sync(0xffffffffu, m1a, o));
    m1b = fmaxf(m1b, __shfl_xor_sync(0xffffffffu, m1b, o));
    m2a = fmaxf(m2a, __shfl_xor_sync(0xffffffffu, m2a, o));
    m2b = fmaxf(m2b, __shfl_xor_sync(0xffffffffu, m2b, o));
    l1a += __shfl_xor_sync(0xffffffffu, l1a, o);
    l1b += __shfl_xor_sync(0xffffffffu, l1b, o);
    l2a += __shfl_xor_sync(0xffffffffu, l2a, o);
    l2b += __shfl_xor_sync(0xffffffffu, l2b, o);
  }
  const float inv0 = 1.0f / (pi0 * ex2(-m1a) * l1a +
                             pi1 * ex2(-m2a) * l2a + 1e-6f);
  const float inv1 = 1.0f / (pi0 * ex2(-m1b) * l1b +
                             pi1 * ex2(-m2b) * l2b + 1e-6f);
  const float rq1a2 = rq1a + lp0 - m1a, rq1b2 = rq1b + lp0 - m1b;
  const float rq2a2 = rq2a + lp1 - m2a, rq2b2 = rq2b + lp1 - m2b;

  // ====== pass 2 ======
  float cctx[4][4];
#pragma unroll
  for (int i = 0; i < 4; i++)
#pragma unroll
    for (int j = 0; j < 4; j++) cctx[i][j] = 0.f;

  uint32_t eh[4], el[4];

  for (int kt = 0; kt < 8; kt++) {
    __syncthreads();
    LOAD_K(kt * 128)
    {
      const size_t vg = ((size_t)bh * 8 + kt) * (kD * 64);
      for (int i = tid; i < 512; i += 256) {
        const int row = i >> 4, c4 = (i & 15) << 2;
        *(uint4*)&Vth[row * 72 + c4] = *(const uint4*)&g_vth[vg + (row << 6) + c4];
        *(uint4*)&Vtl[row * 72 + c4] = *(const uint4*)&g_vtl[vg + (row << 6) + c4];
      }
    }
    __syncthreads();

#pragma unroll 2
    for (int nt = 0; nt < 16; nt++) {
      const int rb = ((nt * 8 + g) << 4) + t * 4;
      const int col = kt * 128 + nt * 8 + 2 * t;
      const float2 cc1 = *(const float2*)&colc1[col];
      const float2 cc2 = *(const float2*)&colc2[col];
      float c1[4], c2[4];
      score6(c1, aqh, aql, K1h, K1l, rb);
      score6(c2, aqh, aql, K2h, K2l, rb);
      float p00 = (ex2(fmaf(kTC1, c1[0], cc1.x + rq1a2))
                 + ex2(fmaf(kTC2, c2[0], cc2.x + rq2a2))) * inv0;
      float p01 = (ex2(fmaf(kTC1, c1[1], cc1.y + rq1a2))
                 + ex2(fmaf(kTC2, c2[1], cc2.y + rq2a2))) * inv0;
      float p10 = (ex2(fmaf(kTC1, c1[2], cc1.x + rq1b2))
                 + ex2(fmaf(kTC2, c2[2], cc2.x + rq2b2))) * inv1;
      float p11 = (ex2(fmaf(kTC1, c1[3], cc1.y + rq1b2))
                 + ex2(fmaf(kTC2, c2[3], cc2.y + rq2b2))) * inv1;

      const size_t pb = ((size_t)bh * kS + q0 + R0) * kS + col;
      __stcs((float2*)&out_probs[pb], make_float2(p00, p01));
      __stcs((float2*)&out_probs[pb + 8 * kS], make_float2(p10, p11));

      if ((nt & 1) == 0) {
        split2(p00, p01, eh[0], el[0]);
        split2(p10, p11, eh[1], el[1]);
      } else {
        split2(p00, p01, eh[2], el[2]);
        split2(p10, p11, eh[3], el[3]);
        const int ks = nt >> 1;
#pragma unroll
        for (int nd = 0; nd < 4; nd++) {
          const int vb = (nd * 8 + g) * 72 + 8 * ks + 2 * t;
          uint2 vh = *(const uint2*)&Vth[vb];
          uint2 vl = *(const uint2*)&Vtl[vb];
          mma_bf16(cctx[nd], eh, vh.x, vh.y);
          mma_bf16(cctx[nd], eh, vl.x, vl.y);
          mma_bf16(cctx[nd], el, vh.x, vh.y);
        }
      }
    }
  }

#pragma unroll
  for (int nd = 0; nd < 4; nd++) {
    const int d = nd * 8 + 2 * t;
    *(float2*)&out_ctx[((size_t)b * kS + q0 + R0) * kAH + h * kD + d] =
        make_float2(cctx[nd][0], cctx[nd][1]);
    *(float2*)&out_ctx[((size_t)b * kS + q0 + R1) * kAH + h * kD + d] =
        make_float2(cctx[nd][2], cctx[nd][3]);
  }
#undef LOAD_K
}

// ---------------------------------------------------------------------------
extern "C" void kernel_launch(void* const* d_in, const int* in_sizes, int n_in,
                              void* d_out, int out_size) {
  (void)in_sizes; (void)n_in; (void)out_size;
  const float* hs   = (const float*)d_in[0];
  const float* mask = (const float*)d_in[1];
  const float* Wq   = (const float*)d_in[2];
  const float* bq   = (const float*)d_in[3];
  const float* Wk1  = (const float*)d_in[4];
  const float* bk1  = (const float*)d_in[5];
  const float* Wk2  = (const float*)d_in[6];
  const float* bk2  = (const float*)d_in[7];
  const float* Wv   = (const float*)d_in[8];
  const float* bv   = (const float*)d_in[9];
  const float* pi   = (const float*)d_in[10];

  float* out_ctx   = (float*)d_out;
  float* out_probs = out_ctx + (size_t)kB * kS * kAH;

  cudaFuncSetAttribute(attn_kernel, cudaFuncAttributeMaxDynamicSharedMemorySize,
                       kAttnSmemBytes);

  const int total_warps = kMB * kKC + 4 * kNB * kKC;
  presplit_kernel<<<(total_warps + 7) / 8, 256>>>(hs, Wq, Wk1, Wk2, Wv);

  dim3 pgrid(kAH / 64, (kB * kS) / 128, 4);   // (6, 32, 4) = 768 CTAs
  proj_kernel<<<pgrid, 256>>>(bq, bk1, bk2, bv);
  attn_kernel<<<dim3(kS / 128, kBH), 256, kAttnSmemBytes>>>(
      mask, pi, out_ctx, out_probs);
}

// round 17
// speedup vs baseline: 1.0904x; 1.0029x over previous
#include <cuda_runtime.h>
#include <cuda_bf16.h>
#include <cstdint>

// ---------------------------------------------------------------------------
// MGKBertSelfAttention: B=4, S=1024, HID=768, H=12, D=32, AH=384
// out = [ctx (B,S,AH) ; probs (B,H,S,S)]  fp32
// mma.sync m16n8k16 bf16, 2-term hi/lo split (3-product, fp32-equiv precision).
// R17: R16 + interleaved W fragments (uint4 {h0,h1,l0,l1}) -> proj B loads
// are 4x LDG.128 per k-chunk instead of 8x LDG.64.
// ---------------------------------------------------------------------------

namespace {
constexpr int kB = 4, kS = 1024, kHid = 768, kH = 12, kD = 32, kAH = 384;
constexpr int kBH = kB * kH;                       // 48
constexpr float kScaling = 0.17677669529663687f;   // 32^-0.5
constexpr float kC1 = 0.5f * kScaling;
constexpr float kC2 = 0.75f * kScaling;
constexpr float kLog2e = 1.4426950408889634f;
constexpr float kC1L = kC1 * kLog2e;
constexpr float kC2L = kC2 * kLog2e;
constexpr float kTC1 = 2.0f * kC1L;
constexpr float kTC2 = 2.0f * kC2L;

constexpr int kMB = (kB * kS) / 16;   // 256 m-blocks (16 rows)
constexpr int kKC = kHid / 16;        // 48 k-chunks
constexpr int kNB = kAH / 8;          // 48 n-blocks (8 cols)

// attn smem layout (u32 units) — identical to R12
constexpr int U_COLC1 = 0;
constexpr int U_COLC2 = 1024;
constexpr int U_K1H   = 2048;
constexpr int U_K1L   = U_K1H + 2048;
constexpr int U_K2H   = U_K1L + 2048;
constexpr int U_K2L   = U_K2H + 2048;
constexpr int U_VTH   = U_K2L + 2048;
constexpr int U_VTL   = U_VTH + 2304;
constexpr int kAttnSmemU32 = U_VTL + 2304;
constexpr int kAttnSmemBytes = kAttnSmemU32 * 4;    // 59648 B
}

// Scratch (device globals; allocation is forbidden)
__device__ float    g_q  [kBH * kS * kD];
__device__ uint32_t g_k1h[kBH * kS * 16];
__device__ uint32_t g_k1l[kBH * kS * 16];
__device__ uint32_t g_k2h[kBH * kS * 16];
__device__ uint32_t g_k2l[kBH * kS * 16];
__device__ uint32_t g_vth[kBH * 8 * kD * 64];
__device__ uint32_t g_vtl[kBH * 8 * kD * 64];
__device__ float    g_nq [kBH * kS];
__device__ float    g_nk1[kBH * kS];
__device__ float    g_nk2[kBH * kS];
// fragment-major pre-split operands
__device__ uint32_t g_xfh[kMB * kKC * 32 * 4];
__device__ uint32_t g_xfl[kMB * kKC * 32 * 4];
__device__ uint4    g_wf [4 * kNB * kKC * 32];      // {h0,h1,l0,l1} per lane

// ---------------------------------------------------------------------------
// helpers
// ---------------------------------------------------------------------------
__device__ __forceinline__ float ex2(float x) {
  float r;
  asm("ex2.approx.f32 %0, %1;" : "=f"(r) : "f"(x));
  return r;
}
__device__ __forceinline__ void split2(float x, float y, uint32_t& h, uint32_t& l) {
  __nv_bfloat16 bx = __float2bfloat16_rn(x);
  __nv_bfloat16 by = __float2bfloat16_rn(y);
  float rx = x - __bfloat162float(bx);
  float ry = y - __bfloat162float(by);
  __nv_bfloat16 lx = __float2bfloat16_rn(rx);
  __nv_bfloat16 ly = __float2bfloat16_rn(ry);
  h = (uint32_t)__bfloat16_as_ushort(bx) | ((uint32_t)__bfloat16_as_ushort(by) << 16);
  l = (uint32_t)__bfloat16_as_ushort(lx) | ((uint32_t)__bfloat16_as_ushort(ly) << 16);
}
__device__ __forceinline__ void mma_bf16(float* c, const uint32_t* a,
                                         uint32_t b0, uint32_t b1) {
  asm volatile(
      "mma.sync.aligned.m16n8k16.row.col.f32.bf16.bf16.f32 "
      "{%0,%1,%2,%3}, {%4,%5,%6,%7}, {%8,%9}, {%0,%1,%2,%3};\n"
      : "+f"(c[0]), "+f"(c[1]), "+f"(c[2]), "+f"(c[3])
      : "r"(a[0]), "r"(a[1]), "r"(a[2]), "r"(a[3]), "r"(b0), "r"(b1));
}

// ---------------------------------------------------------------------------
// Pre-split kernel: X unchanged; W stored interleaved uint4 {h0,h1,l0,l1}.
// ---------------------------------------------------------------------------
__global__ __launch_bounds__(256) void presplit_kernel(
    const float* __restrict__ X,
    const float* __restrict__ Wq, const float* __restrict__ Wk1,
    const float* __restrict__ Wk2, const float* __restrict__ Wv)
{
  const int wg = blockIdx.x * 8 + (threadIdx.x >> 5);
  const int lane = threadIdx.x & 31;
  const int g = lane >> 2, t = lane & 3;

  if (wg < kMB * kKC) {
    const int mb = wg / kKC, kc = wg % kKC;
    const float* p0 = X + (size_t)(mb * 16 + g) * kHid + kc * 16 + 2 * t;
    const float* p1 = p0 + 8 * kHid;
    float2 v00 = *(const float2*)p0;
    float2 v01 = *(const float2*)(p0 + 8);
    float2 v10 = *(const float2*)p1;
    float2 v11 = *(const float2*)(p1 + 8);
    uint4 hv, lv;
    split2(v00.x, v00.y, hv.x, lv.x);
    split2(v10.x, v10.y, hv.y, lv.y);
    split2(v01.x, v01.y, hv.z, lv.z);
    split2(v11.x, v11.y, hv.w, lv.w);
    const size_t o = ((size_t)wg * 32 + lane) * 4;
    *(uint4*)&g_xfh[o] = hv;
    *(uint4*)&g_xfl[o] = lv;
  } else {
    const int r = wg - kMB * kKC;
    if (r >= 4 * kNB * kKC) return;
    const int sel = r / (kNB * kKC);
    const int rr = r % (kNB * kKC);
    const int nb = rr / kKC, kc = rr % kKC;
    const float* W = (sel == 0) ? Wq : (sel == 1) ? Wk1 : (sel == 2) ? Wk2 : Wv;
    const float* p = W + (size_t)(nb * 8 + g) * kHid + kc * 16 + 2 * t;
    float2 v0 = *(const float2*)p;
    float2 v1 = *(const float2*)(p + 8);
    uint4 f;
    split2(v0.x, v0.y, f.x, f.z);   // h0 -> x, l0 -> z
    split2(v1.x, v1.y, f.y, f.w);   // h1 -> y, l1 -> w
    g_wf[(size_t)r * 32 + lane] = f;
  }
}

// ---------------------------------------------------------------------------
// Streaming projection GEMM: 2-stage register prefetch, uint4 B loads.
// ---------------------------------------------------------------------------
__global__ __launch_bounds__(256, 2) void proj_kernel(
    const float* __restrict__ bq, const float* __restrict__ bk1,
    const float* __restrict__ bk2, const float* __restrict__ bv)
{
  const int sel = blockIdx.z;
  const float* bias = (sel == 0) ? bq : (sel == 1) ? bk1 : (sel == 2) ? bk2 : bv;

  const int tid = threadIdx.x;
  const int w = tid >> 5, lane = tid & 31;
  const int g = lane >> 2, t = lane & 3;
  const int wm = (w & 3) * 32, wn = (w >> 2) * 32;
  const int m0 = blockIdx.y * 128, n0 = blockIdx.x * 64;

  const int mb0 = (m0 + wm) >> 4;
  const int nb0 = (n0 + wn) >> 3;
  const size_t xbase0 = (((size_t)mb0 * kKC) * 32 + lane) * 4;
  const size_t xbase1 = ((((size_t)mb0 + 1) * kKC) * 32 + lane) * 4;
  const size_t wsel = (size_t)sel * kNB * kKC * 32;
  size_t wbase[4];
#pragma unroll
  for (int nc = 0; nc < 4; nc++)
    wbase[nc] = wsel + ((size_t)(nb0 + nc) * kKC) * 32 + lane;

  float c[2][4][4];
#pragma unroll
  for (int i = 0; i < 2; i++)
#pragma unroll
    for (int j = 0; j < 4; j++)
#pragma unroll
      for (int k = 0; k < 4; k++) c[i][j][k] = 0.f;

  // double-buffered fragment registers
  uint4 ah[2][2], al[2][2];
  uint4 bf[2][4];

#define LOAD_FRAGS(buf, kc)                                                   \
  {                                                                           \
    ah[buf][0] = *(const uint4*)&g_xfh[xbase0 + (size_t)(kc) * 128];          \
    al[buf][0] = *(const uint4*)&g_xfl[xbase0 + (size_t)(kc) * 128];          \
    ah[buf][1] = *(const uint4*)&g_xfh[xbase1 + (size_t)(kc) * 128];          \
    al[buf][1] = *(const uint4*)&g_xfl[xbase1 + (size_t)(kc) * 128];          \
    _Pragma("unroll")                                                         \
    for (int nc = 0; nc < 4; nc++)                                            \
      bf[buf][nc] = g_wf[wbase[nc] + (size_t)(kc) * 32];                      \
  }

#define DO_MMAS(buf)                                                          \
  {                                                                           \
    _Pragma("unroll")                                                         \
    for (int nc = 0; nc < 4; nc++) {                                          \
      _Pragma("unroll")                                                       \
      for (int tm = 0; tm < 2; tm++) {                                        \
        mma_bf16(c[tm][nc], (const uint32_t*)&ah[buf][tm],                    \
                 bf[buf][nc].x, bf[buf][nc].y);                               \
        mma_bf16(c[tm][nc], (const uint32_t*)&ah[buf][tm],                    \
                 bf[buf][nc].z, bf[buf][nc].w);                               \
        mma_bf16(c[tm][nc], (const uint32_t*)&al[buf][tm],                    \
                 bf[buf][nc].x, bf[buf][nc].y);                               \
      }                                                                       \
    }                                                                         \
  }

  LOAD_FRAGS(0, 0)
#pragma unroll 4
  for (int kc = 0; kc < kKC; kc += 2) {
    LOAD_FRAGS(1, kc + 1)
    DO_MMAS(0)
    if (kc + 2 < kKC) LOAD_FRAGS(0, kc + 2)
    DO_MMAS(1)
  }
#undef LOAD_FRAGS
#undef DO_MMAS

  const int head = (n0 + wn) >> 5;
#pragma unroll
  for (int nc = 0; nc < 4; nc++) {
    const float bb0 = bias[n0 + wn + nc * 8 + 2 * t];
    const float bb1 = bias[n0 + wn + nc * 8 + 2 * t + 1];
#pragma unroll
    for (int tm = 0; tm < 2; tm++) {
      c[tm][nc][0] += bb0; c[tm][nc][1] += bb1;
      c[tm][nc][2] += bb0; c[tm][nc][3] += bb1;
    }
  }

  if (sel < 3) {
    float* nrm = (sel == 0) ? g_nq : (sel == 1) ? g_nk1 : g_nk2;
    float ps[2][2] = {{0.f, 0.f}, {0.f, 0.f}};
#pragma unroll
    for (int tm = 0; tm < 2; tm++)
#pragma unroll
      for (int nc = 0; nc < 4; nc++) {
        ps[tm][0] = fmaf(c[tm][nc][0], c[tm][nc][0],
                    fmaf(c[tm][nc][1], c[tm][nc][1], ps[tm][0]));
        ps[tm][1] = fmaf(c[tm][nc][2], c[tm][nc][2],
                    fmaf(c[tm][nc][3], c[tm][nc][3], ps[tm][1]));
      }
#pragma unroll
    for (int tm = 0; tm < 2; tm++)
#pragma unroll
      for (int hh = 0; hh < 2; hh++) {
#pragma unroll
        for (int o = 1; o < 4; o <<= 1)
          ps[tm][hh] += __shfl_xor_sync(0xffffffffu, ps[tm][hh], o);
      }
    if (t == 0) {
#pragma unroll
      for (int tm = 0; tm < 2; tm++)
#pragma unroll
        for (int hh = 0; hh < 2; hh++) {
          const int r = m0 + wm + tm * 16 + g + hh * 8;
          const int b = r >> 10, s = r & 1023;
          nrm[(b * kH + head) * kS + s] = ps[tm][hh];
        }
    }
  }

  if (sel == 0) {
#pragma unroll
    for (int tm = 0; tm < 2; tm++)
#pragma unroll
      for (int nc = 0; nc < 4; nc++) {
        const int d = nc * 8 + 2 * t;
        const int r0 = m0 + wm + tm * 16 + g;
        {
          const int b = r0 >> 10, s = r0 & 1023;
          *(float2*)&g_q[(((size_t)b * kH + head) * kS + s) * kD + d] =
              make_float2(c[tm][nc][0], c[tm][nc][1]);
        }
        {
          const int r1 = r0 + 8;
          const int b = r1 >> 10, s = r1 & 1023;
          *(float2*)&g_q[(((size_t)b * kH + head) * kS + s) * kD + d] =
              make_float2(c[tm][nc][2], c[tm][nc][3]);
        }
      }
  } else if (sel < 3) {
    uint32_t* outh = (sel == 1) ? g_k1h : g_k2h;
    uint32_t* outl = (sel == 1) ? g_k1l : g_k2l;
#pragma unroll
    for (int tm = 0; tm < 2; tm++)
#pragma unroll
      for (int nc = 0; nc < 4; nc++) {
        const int pos = t * 4 + nc;
        const int r0 = m0 + wm + tm * 16 + g;
        uint32_t h, l;
        {
          const int b = r0 >> 10, s = r0 & 1023;
          split2(c[tm][nc][0], c[tm][nc][1], h, l);
          const size_t o = ((size_t)(b * kH + head) * kS + s) * 16 + pos;
          outh[o] = h; outl[o] = l;
        }
        {
          const int r1 = r0 + 8;
          const int b = r1 >> 10, s = r1 & 1023;
          split2(c[tm][nc][2], c[tm][nc][3], h, l);
          const size_t o = ((size_t)(b * kH + head) * kS + s) * 16 + pos;
          outh[o] = h; outl[o] = l;
        }
      }
  } else {
#pragma unroll
    for (int tm = 0; tm < 2; tm++)
#pragma unroll
      for (int nc = 0; nc < 4; nc++)
#pragma unroll
        for (int hh = 0; hh < 2; hh++) {
          float v0 = c[tm][nc][hh * 2];
          float v1 = c[tm][nc][hh * 2 + 1];
          float v0o = __shfl_down_sync(0xffffffffu, v0, 4);
          float v1o = __shfl_down_sync(0xffffffffu, v1, 4);
          if ((g & 1) == 0) {
            const int m = m0 + wm + tm * 16 + g + hh * 8;
            const int b = m >> 10, s = m & 1023;
            const int kt = s >> 7;
            const int jp = (s & 127) >> 1;
            const int pos = (jp & ~7) + ((jp & 3) << 1) + ((jp >> 2) & 1);
            const int d = nc * 8 + 2 * t;
            const size_t base = ((size_t)(b * kH + head) * 8 + kt) * kD;
            uint32_t h0, l0, h1, l1;
            split2(v0, v0o, h0, l0);
            split2(v1, v1o, h1, l1);
            g_vth[(base + d) * 64 + pos] = h0;
            g_vtl[(base + d) * 64 + pos] = l0;
            g_vth[(base + d + 1) * 64 + pos] = h1;
            g_vtl[(base + d + 1) * 64 + pos] = l1;
          }
        }
  }
}

// ---------------------------------------------------------------------------
// Fused attention (byte-identical to R12/R16).
// ---------------------------------------------------------------------------
__device__ __forceinline__ void score6(float* c,
                                       const uint32_t aqh[2][4],
                                       const uint32_t aql[2][4],
                                       const uint32_t* __restrict__ Kh,
                                       const uint32_t* __restrict__ Kl,
                                       int rb) {
  uint4 fh = *(const uint4*)&Kh[rb];
  uint4 fl = *(const uint4*)&Kl[rb];
  c[0] = c[1] = c[2] = c[3] = 0.f;
  mma_bf16(c, aqh[0], fh.x, fh.y);
  mma_bf16(c, aqh[0], fl.x, fl.y);
  mma_bf16(c, aql[0], fh.x, fh.y);
  mma_bf16(c, aqh[1], fh.z, fh.w);
  mma_bf16(c, aqh[1], fl.z, fl.w);
  mma_bf16(c, aql[1], fh.z, fh.w);
}

__global__ __launch_bounds__(256, 3) void attn_kernel(
    const float* __restrict__ mask, const float* __restrict__ pi,
    float* __restrict__ out_ctx, float* __restrict__ out_probs)
{
  extern __shared__ uint32_t su[];
  float* colc1 = (float*)(su + U_COLC1);
  float* colc2 = (float*)(su + U_COLC2);
  uint32_t* K1h = su + U_K1H;
  uint32_t* K1l = su + U_K1L;
  uint32_t* K2h = su + U_K2H;
  uint32_t* K2l = su + U_K2L;
  uint32_t* Vth = su + U_VTH;
  uint32_t* Vtl = su + U_VTL;

  const int tid = threadIdx.x;
  const int w = tid >> 5, lane = tid & 31;
  const int g = lane >> 2, t = lane & 3;
  const int R0 = w * 16 + g, R1 = R0 + 8;

  const int qt = blockIdx.x, bh = blockIdx.y;
  const int b = bh / kH, h = bh % kH;
  const int q0 = qt * 128;
  const int nbase = bh * kS;
  const size_t gbase = (size_t)bh * kS * kD;

  const float pi0 = fminf(fmaxf(pi[h],      1e-6f), 2.0f);
  const float pi1 = fminf(fmaxf(pi[kH + h], 1e-6f), 2.0f);
  const float lp0 = __log2f(pi0), lp1 = __log2f(pi1);

  for (int i = tid; i < kS; i += 256) {
    const float mk = mask[b * kS + i] * kLog2e;
    colc1[i] = fmaf(-kC1L, g_nk1[nbase + i], mk);
    colc2[i] = fmaf(-kC2L, g_nk2[nbase + i], mk);
  }

  {
    float* qst = (float*)(su + U_K1H);
    for (int i = tid; i < 1024; i += 256) {
      const int j = i >> 3, dg = (i & 7) * 4;
      float4 v = *(const float4*)&g_q[gbase + (size_t)(q0 + j) * kD + dg];
      qst[j * 33 + dg + 0] = v.x; qst[j * 33 + dg + 1] = v.y;
      qst[j * 33 + dg + 2] = v.z; qst[j * 33 + dg + 3] = v.w;
    }
  }
  __syncthreads();

  uint32_t aqh[2][4], aql[2][4];
  {
    float* qst = (float*)(su + U_K1H);
#pragma unroll
    for (int ks = 0; ks < 2; ks++) {
      const int d0 = 16 * ks + 2 * t;
      split2(qst[R0 * 33 + d0],     qst[R0 * 33 + d0 + 1], aqh[ks][0], aql[ks][0]);
      split2(qst[R1 * 33 + d0],     qst[R1 * 33 + d0 + 1], aqh[ks][1], aql[ks][1]);
      split2(qst[R0 * 33 + d0 + 8], qst[R0 * 33 + d0 + 9], aqh[ks][2], aql[ks][2]);
      split2(qst[R1 * 33 + d0 + 8], qst[R1 * 33 + d0 + 9], aqh[ks][3], aql[ks][3]);
    }
  }
  const float nq0 = g_nq[nbase + q0 + R0];
  const float nq1 = g_nq[nbase + q0 + R1];
  const float rq1a = -kC1L * nq0, rq1b = -kC1L * nq1;
  const float rq2a = -kC2L * nq0, rq2b = -kC2L * nq1;
  __syncthreads();

#define LOAD_K(j0)                                                            \
  {                                                                           \
    const size_t gw = (size_t)(nbase + (j0)) * 16;                            \
    for (int i = tid * 4; i < 2048; i += 1024) {                              \
      *(uint4*)&K1h[i] = *(const uint4*)&g_k1h[gw + i];                       \
      *(uint4*)&K1l[i] = *(const uint4*)&g_k1l[gw + i];                       \
      *(uint4*)&K2h[i] = *(const uint4*)&g_k2h[gw + i];                       \
      *(uint4*)&K2l[i] = *(const uint4*)&g_k2l[gw + i];                       \
    }                                                                         \
  }

  // ====== pass 1 ======
  float m1a = -1e30f, m1b = -1e30f, m2a = -1e30f, m2b = -1e30f;
  float l1a = 0.f, l1b = 0.f, l2a = 0.f, l2b = 0.f;

  for (int kt = 0; kt < 8; kt++) {
    __syncthreads();
    LOAD_K(kt * 128)
    __syncthreads();
#pragma unroll 2
    for (int nt = 0; nt < 16; nt++) {
      const int rb = ((nt * 8 + g) << 4) + t * 4;
      const int col = kt * 128 + nt * 8 + 2 * t;
      const float2 cc1 = *(const float2*)&colc1[col];
      const float2 cc2 = *(const float2*)&colc2[col];
      float c1[4], c2[4];
      score6(c1, aqh, aql, K1h, K1l, rb);
      score6(c2, aqh, aql, K2h, K2l, rb);
      {
        float s0 = fmaf(kTC1, c1[0], cc1.x + rq1a);
        float s1 = fmaf(kTC1, c1[1], cc1.y + rq1a);
        m1a = fmaxf(m1a, fmaxf(s0, s1));
        l1a += ex2(s0) + ex2(s1);
      }
      {
        float s0 = fmaf(kTC1, c1[2], cc1.x + rq1b);
        float s1 = fmaf(kTC1, c1[3], cc1.y + rq1b);
        m1b = fmaxf(m1b, fmaxf(s0, s1));
        l1b += ex2(s0) + ex2(s1);
      }
      {
        float s0 = fmaf(kTC2, c2[0], cc2.x + rq2a);
        float s1 = fmaf(kTC2, c2[1], cc2.y + rq2a);
        m2a = fmaxf(m2a, fmaxf(s0, s1));
        l2a += ex2(s0) + ex2(s1);
      }
      {
        float s0 = fmaf(kTC2, c2[2], cc2.x + rq2b);
        float s1 = fmaf(kTC2, c2[3], cc2.y + rq2b);
        m2b = fmaxf(m2b, fmaxf(s0, s1));
        l2b += ex2(s0) + ex2(s1);
      }
    }
  }
#pragma unroll
  for (int o = 1; o < 4; o <<= 1) {
    m1a = fmaxf(m1a, __shfl_xor_sync(0xffffffffu, m1a, o));
    m1b = fmaxf(m1b, __shfl_xor_sync(0xffffffffu, m1b, o));
    m2a = fmaxf(m2a, __shfl_xor_sync(0xffffffffu, m2a, o));
    m2b = fmaxf(m2b, __shfl_xor_sync(0xffffffffu, m2b, o));
    l1a += __shfl_xor_sync(0xffffffffu, l1a, o);
    l1b += __shfl_xor_sync(0xffffffffu, l1b, o);
    l2a += __shfl_xor_sync(0xffffffffu, l2a, o);
    l2b += __shfl_xor_sync(0xffffffffu, l2b, o);
  }
  const float inv0 = 1.0f / (pi0 * ex2(-m1a) * l1a +
                             pi1 * ex2(-m2a) * l2a + 1e-6f);
  const float inv1 = 1.0f / (pi0 * ex2(-m1b) * l1b +
                             pi1 * ex2(-m2b) * l2b + 1e-6f);
  const float rq1a2 = rq1a + lp0 - m1a, rq1b2 = rq1b + lp0 - m1b;
  const float rq2a2 = rq2a + lp1 - m2a, rq2b2 = rq2b + lp1 - m2b;

  // ====== pass 2 ======
  float cctx[4][4];
#pragma unroll
  for (int i = 0; i < 4; i++)
#pragma unroll
    for (int j = 0; j < 4; j++) cctx[i][j] = 0.f;

  uint32_t eh[4], el[4];

  for (int kt = 0; kt < 8; kt++) {
    __syncthreads();
    LOAD_K(kt * 128)
    {
      const size_t vg = ((size_t)bh * 8 + kt) * (kD * 64);
      for (int i = tid; i < 512; i += 256) {
        const int row = i >> 4, c4 = (i & 15) << 2;
        *(uint4*)&Vth[row * 72 + c4] = *(const uint4*)&g_vth[vg + (row << 6) + c4];
        *(uint4*)&Vtl[row * 72 + c4] = *(const uint4*)&g_vtl[vg + (row << 6) + c4];
      }
    }
    __syncthreads();

#pragma unroll 2
    for (int nt = 0; nt < 16; nt++) {
      const int rb = ((nt * 8 + g) << 4) + t * 4;
      const int col = kt * 128 + nt * 8 + 2 * t;
      const float2 cc1 = *(const float2*)&colc1[col];
      const float2 cc2 = *(const float2*)&colc2[col];
      float c1[4], c2[4];
      score6(c1, aqh, aql, K1h, K1l, rb);
      score6(c2, aqh, aql, K2h, K2l, rb);
      float p00 = (ex2(fmaf(kTC1, c1[0], cc1.x + rq1a2))
                 + ex2(fmaf(kTC2, c2[0], cc2.x + rq2a2))) * inv0;
      float p01 = (ex2(fmaf(kTC1, c1[1], cc1.y + rq1a2))
                 + ex2(fmaf(kTC2, c2[1], cc2.y + rq2a2))) * inv0;
      float p10 = (ex2(fmaf(kTC1, c1[2], cc1.x + rq1b2))
                 + ex2(fmaf(kTC2, c2[2], cc2.x + rq2b2))) * inv1;
      float p11 = (ex2(fmaf(kTC1, c1[3], cc1.y + rq1b2))
                 + ex2(fmaf(kTC2, c2[3], cc2.y + rq2b2))) * inv1;

      const size_t pb = ((size_t)bh * kS + q0 + R0) * kS + col;
      __stcs((float2*)&out_probs[pb], make_float2(p00, p01));
      __stcs((float2*)&out_probs[pb + 8 * kS], make_float2(p10, p11));

      if ((nt & 1) == 0) {
        split2(p00, p01, eh[0], el[0]);
        split2(p10, p11, eh[1], el[1]);
      } else {
        split2(p00, p01, eh[2], el[2]);
        split2(p10, p11, eh[3], el[3]);
        const int ks = nt >> 1;
#pragma unroll
        for (int nd = 0; nd < 4; nd++) {
          const int vb = (nd * 8 + g) * 72 + 8 * ks + 2 * t;
          uint2 vh = *(const uint2*)&Vth[vb];
          uint2 vl = *(const uint2*)&Vtl[vb];
          mma_bf16(cctx[nd], eh, vh.x, vh.y);
          mma_bf16(cctx[nd], eh, vl.x, vl.y);
          mma_bf16(cctx[nd], el, vh.x, vh.y);
        }
      }
    }
  }

#pragma unroll
  for (int nd = 0; nd < 4; nd++) {
    const int d = nd * 8 + 2 * t;
    *(float2*)&out_ctx[((size_t)b * kS + q0 + R0) * kAH + h * kD + d] =
        make_float2(cctx[nd][0], cctx[nd][1]);
    *(float2*)&out_ctx[((size_t)b * kS + q0 + R1) * kAH + h * kD + d] =
        make_float2(cctx[nd][2], cctx[nd][3]);
  }
#undef LOAD_K
}

// ---------------------------------------------------------------------------
extern "C" void kernel_launch(void* const* d_in, const int* in_sizes, int n_in,
                              void* d_out, int out_size) {
  (void)in_sizes; (void)n_in; (void)out_size;
  const float* hs   = (const float*)d_in[0];
  const float* mask = (const float*)d_in[1];
  const float* Wq   = (const float*)d_in[2];
  const float* bq   = (const float*)d_in[3];
  const float* Wk1  = (const float*)d_in[4];
  const float* bk1  = (const float*)d_in[5];
  const float* Wk2  = (const float*)d_in[6];
  const float* bk2  = (const float*)d_in[7];
  const float* Wv   = (const float*)d_in[8];
  const float* bv   = (const float*)d_in[9];
  const float* pi   = (const float*)d_in[10];

  float* out_ctx   = (float*)d_out;
  float* out_probs = out_ctx + (size_t)kB * kS * kAH;

  cudaFuncSetAttribute(attn_kernel, cudaFuncAttributeMaxDynamicSharedMemorySize,
                       kAttnSmemBytes);

  const int total_warps = kMB * kKC + 4 * kNB * kKC;
  presplit_kernel<<<(total_warps + 7) / 8, 256>>>(hs, Wq, Wk1, Wk2, Wv);

  dim3 pgrid(kAH / 64, (kB * kS) / 128, 4);   // (6, 32, 4) = 768 CTAs
  proj_kernel<<<pgrid, 256>>>(bq, bk1, bk2, bv);
  attn_kernel<<<dim3(kS / 128, kBH), 256, kAttnSmemBytes>>>(
      mask, pi, out_ctx, out_probs);
}